// round 1
// baseline (speedup 1.0000x reference)
#include <cuda_runtime.h>
#include <math.h>

#define BB 2
#define SS 2048
#define DD 1024
#define HH 16
#define HD 64
#define M1 (BB*SS)      // 4096
#define N1 (3*DD)       // 3072
#define KD DD           // 1024
#define NBH (BB*HH)     // 32
#define SCALE 0.125f

// ---------------- scratch (device globals; no allocations allowed) ----------
__device__ float g_qkv[(size_t)M1 * N1];          // 48 MB: [4096, 3072]
__device__ float g_q[(size_t)NBH * SS * HD];      // 16 MB: [B,H,S,HD]
__device__ float g_k[(size_t)NBH * SS * HD];
__device__ float g_v[(size_t)NBH * SS * HD];
__device__ float g_ao[(size_t)BB * SS * DD];      // 16 MB: [B,S,D]

// ---------------- generic NT SGEMM: C[M,N] = A[M,K] @ W[N,K]^T + bias -------
// 128x128 tile, BK=16, 256 threads, 8x8 micro-tile per thread.
__global__ __launch_bounds__(256) void sgemm_nt_bias(
    const float* __restrict__ A, const float* __restrict__ W,
    const float* __restrict__ bias, float* __restrict__ C,
    int M, int N, int K)
{
    __shared__ float As[16][128];
    __shared__ float Bs[16][128];
    const int tid = threadIdx.x;
    const int ty = tid >> 4;           // 0..15
    const int tx = tid & 15;           // 0..15
    const int bm = blockIdx.y << 7;
    const int bn = blockIdx.x << 7;
    const int lr = tid >> 2;           // 0..63
    const int lc = (tid & 3) << 2;     // 0,4,8,12

    float acc[8][8];
#pragma unroll
    for (int i = 0; i < 8; i++)
#pragma unroll
        for (int j = 0; j < 8; j++) acc[i][j] = 0.f;

    for (int k0 = 0; k0 < K; k0 += 16) {
        float4 a0 = *(const float4*)(A + (size_t)(bm + lr) * K + k0 + lc);
        float4 a1 = *(const float4*)(A + (size_t)(bm + lr + 64) * K + k0 + lc);
        float4 b0 = *(const float4*)(W + (size_t)(bn + lr) * K + k0 + lc);
        float4 b1 = *(const float4*)(W + (size_t)(bn + lr + 64) * K + k0 + lc);
        As[lc + 0][lr] = a0.x; As[lc + 1][lr] = a0.y; As[lc + 2][lr] = a0.z; As[lc + 3][lr] = a0.w;
        As[lc + 0][lr + 64] = a1.x; As[lc + 1][lr + 64] = a1.y; As[lc + 2][lr + 64] = a1.z; As[lc + 3][lr + 64] = a1.w;
        Bs[lc + 0][lr] = b0.x; Bs[lc + 1][lr] = b0.y; Bs[lc + 2][lr] = b0.z; Bs[lc + 3][lr] = b0.w;
        Bs[lc + 0][lr + 64] = b1.x; Bs[lc + 1][lr + 64] = b1.y; Bs[lc + 2][lr + 64] = b1.z; Bs[lc + 3][lr + 64] = b1.w;
        __syncthreads();
#pragma unroll
        for (int kk = 0; kk < 16; kk++) {
            float a[8], b[8];
            *(float4*)(a)     = *(float4*)&As[kk][ty << 3];
            *(float4*)(a + 4) = *(float4*)&As[kk][(ty << 3) + 4];
            *(float4*)(b)     = *(float4*)&Bs[kk][tx << 3];
            *(float4*)(b + 4) = *(float4*)&Bs[kk][(tx << 3) + 4];
#pragma unroll
            for (int i = 0; i < 8; i++)
#pragma unroll
                for (int j = 0; j < 8; j++) acc[i][j] += a[i] * b[j];
        }
        __syncthreads();
    }

#pragma unroll
    for (int i = 0; i < 8; i++) {
        int row = bm + (ty << 3) + i;
#pragma unroll
        for (int j = 0; j < 8; j++) {
            int col = bn + (tx << 3) + j;
            C[(size_t)row * N + col] = acc[i][j] + bias[col];
        }
    }
}

// ---------------- RoPE + L2-normalize + scatter to [B,H,S,HD] ---------------
// One warp per (b,h,s); lane f handles the interleaved pair (2f, 2f+1).
__global__ __launch_bounds__(128) void rope_kernel()
{
    const int f = threadIdx.x;                    // 0..31
    const int rid = blockIdx.x * 4 + threadIdx.y; // 0 .. B*H*S-1
    const int bh = rid >> 11;                     // / S (S = 2048)
    const int s  = rid & (SS - 1);
    const int b  = bh >> 4;
    const int h  = bh & 15;

    // inv_freq = 10000^(-f/32), theta = s * inv_freq (high precision; sin/cos fp32)
    double invd = exp(-(double)f * (9.210340371976184 / 32.0));
    float theta = (float)((double)s * invd);
    float sn, cs;
    sincosf(theta, &sn, &cs);

    const float* src = g_qkv + (size_t)(b * SS + s) * N1 + h * HD;
    const size_t dst = ((size_t)bh * SS + s) * HD;

    // Q
    {
        float e = src[2 * f], o = src[2 * f + 1];
        float re = e * cs - o * sn;
        float ro = e * sn + o * cs;
        float sq = re * re + ro * ro;
#pragma unroll
        for (int msk = 16; msk > 0; msk >>= 1) sq += __shfl_xor_sync(0xffffffffu, sq, msk);
        float inv = 1.0f / fmaxf(sqrtf(sq), 1e-12f);
        g_q[dst + 2 * f] = re * inv;
        g_q[dst + 2 * f + 1] = ro * inv;
    }
    // K
    {
        float e = src[DD + 2 * f], o = src[DD + 2 * f + 1];
        float re = e * cs - o * sn;
        float ro = e * sn + o * cs;
        float sq = re * re + ro * ro;
#pragma unroll
        for (int msk = 16; msk > 0; msk >>= 1) sq += __shfl_xor_sync(0xffffffffu, sq, msk);
        float inv = 1.0f / fmaxf(sqrtf(sq), 1e-12f);
        g_k[dst + 2 * f] = re * inv;
        g_k[dst + 2 * f + 1] = ro * inv;
    }
    // V (plain transpose/copy)
    g_v[dst + 2 * f] = src[2 * DD + 2 * f];
    g_v[dst + 2 * f + 1] = src[2 * DD + 2 * f + 1];
}

// ---------------- flash attention, 64x64 tiles, online softmax --------------
// grid: (S/64, B*H). 256 threads, 4x4 fragment per thread.
// Smem: Qs (d-major), KP (K tile d-major, reused as P tile j-major), Vs.
__global__ __launch_bounds__(256) void attn_kernel(float* __restrict__ Oo)
{
    __shared__ float Qs[64][64];   // [d][i]
    __shared__ float KP[64][64];   // K phase: [d][j]; P phase: [j][i]
    __shared__ float Vs[64][64];   // [j][d]

    const int tid = threadIdx.x;
    const int ty = tid >> 4;       // fragment rows 4*ty..+3
    const int tx = tid & 15;       // fragment cols 4*tx..+3
    const int bh = blockIdx.y;
    const int b = bh >> 4, h = bh & 15;
    const int q0 = blockIdx.x << 6;

    const float* Qp = g_q + (size_t)bh * SS * HD;
    const float* Kp = g_k + (size_t)bh * SS * HD;
    const float* Vp = g_v + (size_t)bh * SS * HD;

    // load Q tile transposed
#pragma unroll
    for (int it = 0; it < 4; it++) {
        int idx = tid + 256 * it;
        int r = idx >> 4;
        int c = (idx & 15) << 2;
        float4 qv = *(const float4*)(Qp + (size_t)(q0 + r) * HD + c);
        Qs[c + 0][r] = qv.x; Qs[c + 1][r] = qv.y; Qs[c + 2][r] = qv.z; Qs[c + 3][r] = qv.w;
    }

    float m[4], l[4], o[4][4];
#pragma unroll
    for (int r = 0; r < 4; r++) {
        m[r] = -1e30f; l[r] = 0.f;
#pragma unroll
        for (int c = 0; c < 4; c++) o[r][c] = 0.f;
    }
    __syncthreads();

    for (int j0 = 0; j0 < SS; j0 += 64) {
        // load K (transposed) and V (direct)
#pragma unroll
        for (int it = 0; it < 4; it++) {
            int idx = tid + 256 * it;
            int r = idx >> 4;
            int c = (idx & 15) << 2;
            float4 kv = *(const float4*)(Kp + (size_t)(j0 + r) * HD + c);
            KP[c + 0][r] = kv.x; KP[c + 1][r] = kv.y; KP[c + 2][r] = kv.z; KP[c + 3][r] = kv.w;
            float4 vv = *(const float4*)(Vp + (size_t)(j0 + r) * HD + c);
            *(float4*)&Vs[r][c] = vv;
        }
        __syncthreads();

        // S = Q K^T (scaled)
        float s[4][4];
#pragma unroll
        for (int r = 0; r < 4; r++)
#pragma unroll
            for (int c = 0; c < 4; c++) s[r][c] = 0.f;
#pragma unroll
        for (int d = 0; d < 64; d++) {
            float4 qa = *(float4*)&Qs[d][ty << 2];
            float4 kb = *(float4*)&KP[d][tx << 2];
            float av[4] = {qa.x, qa.y, qa.z, qa.w};
            float bv[4] = {kb.x, kb.y, kb.z, kb.w};
#pragma unroll
            for (int r = 0; r < 4; r++)
#pragma unroll
                for (int c = 0; c < 4; c++) s[r][c] += av[r] * bv[c];
        }

        // online softmax stats (row reduce across 16 tx lanes)
        float pr[4][4];
#pragma unroll
        for (int r = 0; r < 4; r++) {
#pragma unroll
            for (int c = 0; c < 4; c++) s[r][c] *= SCALE;
            float mx = fmaxf(fmaxf(s[r][0], s[r][1]), fmaxf(s[r][2], s[r][3]));
#pragma unroll
            for (int msk = 1; msk < 16; msk <<= 1)
                mx = fmaxf(mx, __shfl_xor_sync(0xffffffffu, mx, msk));
            float mn = fmaxf(m[r], mx);
            float sum = 0.f;
#pragma unroll
            for (int c = 0; c < 4; c++) {
                pr[r][c] = __expf(s[r][c] - mn);
                sum += pr[r][c];
            }
#pragma unroll
            for (int msk = 1; msk < 16; msk <<= 1)
                sum += __shfl_xor_sync(0xffffffffu, sum, msk);
            float al = __expf(m[r] - mn);
            l[r] = l[r] * al + sum;
            m[r] = mn;
#pragma unroll
            for (int c = 0; c < 4; c++) o[r][c] *= al;
        }
        __syncthreads();   // everyone done reading KP as K

        // write P transposed into KP: KP[j][i]
#pragma unroll
        for (int r = 0; r < 4; r++)
#pragma unroll
            for (int c = 0; c < 4; c++)
                KP[(tx << 2) + c][(ty << 2) + r] = pr[r][c];
        __syncthreads();

        // O += P @ V
#pragma unroll
        for (int j = 0; j < 64; j++) {
            float4 pa = *(float4*)&KP[j][ty << 2];
            float4 vb = *(float4*)&Vs[j][tx << 2];
            float av[4] = {pa.x, pa.y, pa.z, pa.w};
            float bv[4] = {vb.x, vb.y, vb.z, vb.w};
#pragma unroll
            for (int r = 0; r < 4; r++)
#pragma unroll
                for (int c = 0; c < 4; c++) o[r][c] += av[r] * bv[c];
        }
        __syncthreads();   // before next tile's loads overwrite KP/Vs
    }

    // epilogue: normalize and write to [B,S,D] with col = h*HD + d
    float* Op = Oo + (size_t)b * SS * DD + h * HD;
#pragma unroll
    for (int r = 0; r < 4; r++) {
        int row = q0 + (ty << 2) + r;
        float inv = 1.0f / l[r];
#pragma unroll
        for (int c = 0; c < 4; c++)
            Op[(size_t)row * DD + (tx << 2) + c] = o[r][c] * inv;
    }
}

// ---------------- launch ----------------------------------------------------
extern "C" void kernel_launch(void* const* d_in, const int* in_sizes, int n_in,
                              void* d_out, int out_size)
{
    (void)in_sizes; (void)n_in; (void)out_size;
    const float* tokens = (const float*)d_in[0];
    const float* qkv_w  = (const float*)d_in[1];
    const float* qkv_b  = (const float*)d_in[2];
    const float* out_w  = (const float*)d_in[3];
    const float* out_b  = (const float*)d_in[4];
    float* out = (float*)d_out;

    float *qkv_s, *ao_s;
    cudaGetSymbolAddress((void**)&qkv_s, g_qkv);
    cudaGetSymbolAddress((void**)&ao_s, g_ao);

    // 1) QKV projection: [4096,1024] @ [3072,1024]^T -> [4096,3072]
    sgemm_nt_bias<<<dim3(N1 / 128, M1 / 128), 256>>>(tokens, qkv_w, qkv_b, qkv_s, M1, N1, KD);
    // 2) RoPE + normalize + split into [B,H,S,HD]
    rope_kernel<<<(BB * HH * SS) / 4, dim3(32, 4)>>>();
    // 3) attention -> [B,S,D]
    attn_kernel<<<dim3(SS / 64, NBH), 256>>>(ao_s);
    // 4) output projection: [4096,1024] @ [1024,1024]^T + b -> out
    sgemm_nt_bias<<<dim3(DD / 128, M1 / 128), 256>>>(ao_s, out_w, out_b, out, M1, DD, KD);
}

// round 2
// speedup vs baseline: 2.2412x; 2.2412x over previous
#include <cuda_runtime.h>
#include <math.h>

#define BB 2
#define SS 2048
#define DD 1024
#define HH 16
#define HD 64
#define M1 (BB*SS)      // 4096
#define N1 (3*DD)       // 3072
#define KD DD           // 1024
#define NBH (BB*HH)     // 32
#define SCALE 0.125f

// ---------------- scratch (device globals; no allocations allowed) ----------
__device__ float g_qkv[(size_t)M1 * N1];          // [4096, 3072]
__device__ float g_q[(size_t)NBH * SS * HD];      // [B,H,S,HD] (pre-scaled by 0.125)
__device__ float g_k[(size_t)NBH * SS * HD];
__device__ float g_v[(size_t)NBH * SS * HD];
__device__ float g_ao[(size_t)BB * SS * DD];      // [B,S,D]

// ---------------- tf32 helpers ----------------------------------------------
__device__ __forceinline__ unsigned f2tf(float x) {
    unsigned u;
    asm("cvt.rna.tf32.f32 %0, %1;" : "=r"(u) : "f"(x));
    return u;
}
__device__ __forceinline__ void mma_tf32(float* c,
    unsigned a0, unsigned a1, unsigned a2, unsigned a3,
    unsigned b0, unsigned b1)
{
    asm volatile(
        "mma.sync.aligned.m16n8k8.row.col.f32.tf32.tf32.f32 "
        "{%0,%1,%2,%3},{%4,%5,%6,%7},{%8,%9},{%0,%1,%2,%3};"
        : "+f"(c[0]), "+f"(c[1]), "+f"(c[2]), "+f"(c[3])
        : "r"(a0), "r"(a1), "r"(a2), "r"(a3), "r"(b0), "r"(b1));
}

// ---------------- tf32 GEMM: C[M,N] = A[M,K] @ W[N,K]^T + bias --------------
// 128x128 tile, BK=16, 256 threads (8 warps, 2x4), warp tile 64x32.
#define GP 136   // smem pitch (words) for 128-wide k-major tiles; 136%32==8 -> conflict-free frags
__global__ __launch_bounds__(256) void gemm_tf32_nt(
    const float* __restrict__ A, const float* __restrict__ W,
    const float* __restrict__ bias, float* __restrict__ C,
    int M, int N, int K)
{
    __shared__ unsigned As[2][16 * GP];   // [k][m]
    __shared__ unsigned Bs[2][16 * GP];   // [k][n]

    const int tid = threadIdx.x;
    const int bm = blockIdx.y << 7;
    const int bn = blockIdx.x << 7;
    const int lr  = tid >> 2;            // 0..63 (row within half-tile)
    const int lc4 = (tid & 3) << 2;      // 0,4,8,12 (k base)
    const int w   = tid >> 5;
    const int lane = tid & 31;
    const int wm = (w & 1) << 6;         // 0 / 64
    const int wn = (w >> 1) << 5;        // 0,32,64,96
    const int fr = lane >> 2;            // 0..7
    const int fc = lane & 3;             // 0..3

    float acc[4][4][4];
#pragma unroll
    for (int mt = 0; mt < 4; mt++)
#pragma unroll
        for (int nt = 0; nt < 4; nt++)
#pragma unroll
            for (int i = 0; i < 4; i++) acc[mt][nt][i] = 0.f;

    const float* Ap  = A + (size_t)(bm + lr) * K + lc4;
    const float* Ap2 = Ap + (size_t)64 * K;
    const float* Wp  = W + (size_t)(bn + lr) * K + lc4;
    const float* Wp2 = Wp + (size_t)64 * K;

    // prologue: stage k-tile 0
    {
        float4 a0 = *(const float4*)Ap;
        float4 a1 = *(const float4*)Ap2;
        float4 b0 = *(const float4*)Wp;
        float4 b1 = *(const float4*)Wp2;
        unsigned* as = As[0]; unsigned* bs = Bs[0];
        as[(lc4+0)*GP+lr]=f2tf(a0.x); as[(lc4+1)*GP+lr]=f2tf(a0.y);
        as[(lc4+2)*GP+lr]=f2tf(a0.z); as[(lc4+3)*GP+lr]=f2tf(a0.w);
        as[(lc4+0)*GP+lr+64]=f2tf(a1.x); as[(lc4+1)*GP+lr+64]=f2tf(a1.y);
        as[(lc4+2)*GP+lr+64]=f2tf(a1.z); as[(lc4+3)*GP+lr+64]=f2tf(a1.w);
        bs[(lc4+0)*GP+lr]=f2tf(b0.x); bs[(lc4+1)*GP+lr]=f2tf(b0.y);
        bs[(lc4+2)*GP+lr]=f2tf(b0.z); bs[(lc4+3)*GP+lr]=f2tf(b0.w);
        bs[(lc4+0)*GP+lr+64]=f2tf(b1.x); bs[(lc4+1)*GP+lr+64]=f2tf(b1.y);
        bs[(lc4+2)*GP+lr+64]=f2tf(b1.z); bs[(lc4+3)*GP+lr+64]=f2tf(b1.w);
    }
    __syncthreads();

    const int nk = K >> 4;
    for (int kt = 0; kt < nk; kt++) {
        const int cur = kt & 1;
        float4 na0, na1, nb0, nb1;
        const bool more = (kt + 1 < nk);
        if (more) {
            const int off = (kt + 1) << 4;
            na0 = *(const float4*)(Ap  + off);
            na1 = *(const float4*)(Ap2 + off);
            nb0 = *(const float4*)(Wp  + off);
            nb1 = *(const float4*)(Wp2 + off);
        }
        const unsigned* as = As[cur];
        const unsigned* bs = Bs[cur];
#pragma unroll
        for (int ks = 0; ks < 2; ks++) {
            const int kb = ks << 3;
            unsigned af[4][4], bf[4][2];
#pragma unroll
            for (int mt = 0; mt < 4; mt++) {
                const int m = wm + (mt << 4);
                af[mt][0] = as[(kb+fc  )*GP + m + fr];
                af[mt][1] = as[(kb+fc  )*GP + m + fr + 8];
                af[mt][2] = as[(kb+fc+4)*GP + m + fr];
                af[mt][3] = as[(kb+fc+4)*GP + m + fr + 8];
            }
#pragma unroll
            for (int nt = 0; nt < 4; nt++) {
                const int n = wn + (nt << 3);
                bf[nt][0] = bs[(kb+fc  )*GP + n + fr];
                bf[nt][1] = bs[(kb+fc+4)*GP + n + fr];
            }
#pragma unroll
            for (int mt = 0; mt < 4; mt++)
#pragma unroll
                for (int nt = 0; nt < 4; nt++)
                    mma_tf32(acc[mt][nt], af[mt][0], af[mt][1], af[mt][2], af[mt][3],
                             bf[nt][0], bf[nt][1]);
        }
        if (more) {
            unsigned* asn = As[cur ^ 1]; unsigned* bsn = Bs[cur ^ 1];
            asn[(lc4+0)*GP+lr]=f2tf(na0.x); asn[(lc4+1)*GP+lr]=f2tf(na0.y);
            asn[(lc4+2)*GP+lr]=f2tf(na0.z); asn[(lc4+3)*GP+lr]=f2tf(na0.w);
            asn[(lc4+0)*GP+lr+64]=f2tf(na1.x); asn[(lc4+1)*GP+lr+64]=f2tf(na1.y);
            asn[(lc4+2)*GP+lr+64]=f2tf(na1.z); asn[(lc4+3)*GP+lr+64]=f2tf(na1.w);
            bsn[(lc4+0)*GP+lr]=f2tf(nb0.x); bsn[(lc4+1)*GP+lr]=f2tf(nb0.y);
            bsn[(lc4+2)*GP+lr]=f2tf(nb0.z); bsn[(lc4+3)*GP+lr]=f2tf(nb0.w);
            bsn[(lc4+0)*GP+lr+64]=f2tf(nb1.x); bsn[(lc4+1)*GP+lr+64]=f2tf(nb1.y);
            bsn[(lc4+2)*GP+lr+64]=f2tf(nb1.z); bsn[(lc4+3)*GP+lr+64]=f2tf(nb1.w);
        }
        __syncthreads();
    }

    // epilogue
#pragma unroll
    for (int mt = 0; mt < 4; mt++) {
        const int row = bm + wm + (mt << 4) + fr;
#pragma unroll
        for (int nt = 0; nt < 4; nt++) {
            const int col = bn + wn + (nt << 3) + (fc << 1);
            float2 v0 = make_float2(acc[mt][nt][0] + bias[col], acc[mt][nt][1] + bias[col + 1]);
            float2 v1 = make_float2(acc[mt][nt][2] + bias[col], acc[mt][nt][3] + bias[col + 1]);
            *(float2*)(C + (size_t)row * N + col) = v0;
            *(float2*)(C + (size_t)(row + 8) * N + col) = v1;
        }
    }
}

// ---------------- RoPE + L2-normalize + scatter to [B,H,S,HD] ---------------
// q is additionally pre-scaled by SCALE (exact power of two).
__global__ __launch_bounds__(128) void rope_kernel()
{
    const int f = threadIdx.x;                    // 0..31
    const int rid = blockIdx.x * 4 + threadIdx.y; // 0 .. B*H*S-1
    const int bh = rid >> 11;
    const int s  = rid & (SS - 1);
    const int b  = bh >> 4;
    const int h  = bh & 15;

    double invd = exp(-(double)f * (9.210340371976184 / 32.0));
    float theta = (float)((double)s * invd);
    float sn, cs;
    sincosf(theta, &sn, &cs);

    const float* src = g_qkv + (size_t)(b * SS + s) * N1 + h * HD;
    const size_t dst = ((size_t)bh * SS + s) * HD;

    // Q (scaled by SCALE)
    {
        float e = src[2 * f], o = src[2 * f + 1];
        float re = e * cs - o * sn;
        float ro = e * sn + o * cs;
        float sq = re * re + ro * ro;
#pragma unroll
        for (int msk = 16; msk > 0; msk >>= 1) sq += __shfl_xor_sync(0xffffffffu, sq, msk);
        float inv = SCALE / fmaxf(sqrtf(sq), 1e-12f);
        g_q[dst + 2 * f] = re * inv;
        g_q[dst + 2 * f + 1] = ro * inv;
    }
    // K
    {
        float e = src[DD + 2 * f], o = src[DD + 2 * f + 1];
        float re = e * cs - o * sn;
        float ro = e * sn + o * cs;
        float sq = re * re + ro * ro;
#pragma unroll
        for (int msk = 16; msk > 0; msk >>= 1) sq += __shfl_xor_sync(0xffffffffu, sq, msk);
        float inv = 1.0f / fmaxf(sqrtf(sq), 1e-12f);
        g_k[dst + 2 * f] = re * inv;
        g_k[dst + 2 * f + 1] = ro * inv;
    }
    // V
    g_v[dst + 2 * f] = src[2 * DD + 2 * f];
    g_v[dst + 2 * f + 1] = src[2 * DD + 2 * f + 1];
}

// ---------------- tf32 flash attention --------------------------------------
// grid (S/64, B*H), 128 threads (4 warps). Each warp owns 16 q-rows.
// Buffers: sQV holds Q (start) then V per tile; sKP holds K then P per tile.
#define AP 72   // pitch (words); 72%32==8 -> conflict-free k-group frags
__global__ __launch_bounds__(128) void attn_tf32(float* __restrict__ Oo)
{
    __shared__ unsigned sQV[64 * AP];
    __shared__ unsigned sKP[64 * AP];

    const int tid = threadIdx.x;
    const int w = tid >> 5;
    const int lane = tid & 31;
    const int fr = lane >> 2;
    const int fc = lane & 3;
    const int bh = blockIdx.y;
    const int b = bh >> 4, h = bh & 15;
    const int q0 = blockIdx.x << 6;

    const float* Qp = g_q + (size_t)bh * SS * HD;
    const float* Kp = g_k + (size_t)bh * SS * HD;
    const float* Vp = g_v + (size_t)bh * SS * HD;

    // load Q transposed into sQV: sQV[d][row]
#pragma unroll
    for (int it = 0; it < 4; it++) {
        const int d4 = (w + 4 * it) << 2;
#pragma unroll
        for (int h2 = 0; h2 < 2; h2++) {
            const int r = lane + 32 * h2;
            float4 v = *(const float4*)(Qp + (size_t)(q0 + r) * HD + d4);
            sQV[(d4+0)*AP + r] = f2tf(v.x);
            sQV[(d4+1)*AP + r] = f2tf(v.y);
            sQV[(d4+2)*AP + r] = f2tf(v.z);
            sQV[(d4+3)*AP + r] = f2tf(v.w);
        }
    }
    __syncthreads();

    // extract Q fragments (held in registers for the whole kernel)
    unsigned qf[8][4];
    {
        const int m = w << 4;
#pragma unroll
        for (int ks = 0; ks < 8; ks++) {
            const int kb = ks << 3;
            qf[ks][0] = sQV[(kb+fc  )*AP + m + fr];
            qf[ks][1] = sQV[(kb+fc  )*AP + m + fr + 8];
            qf[ks][2] = sQV[(kb+fc+4)*AP + m + fr];
            qf[ks][3] = sQV[(kb+fc+4)*AP + m + fr + 8];
        }
    }

    float o[8][4];
#pragma unroll
    for (int nt = 0; nt < 8; nt++)
#pragma unroll
        for (int i = 0; i < 4; i++) o[nt][i] = 0.f;
    float mA = -1e30f, mB = -1e30f, lA = 0.f, lB = 0.f;

    for (int j0 = 0; j0 < SS; j0 += 64) {
        __syncthreads();   // previous tile's smem reads (incl. Q frag extraction) done

        // K transposed -> sKP[d][kv]
#pragma unroll
        for (int it = 0; it < 4; it++) {
            const int d4 = (w + 4 * it) << 2;
#pragma unroll
            for (int h2 = 0; h2 < 2; h2++) {
                const int r = lane + 32 * h2;
                float4 v = *(const float4*)(Kp + (size_t)(j0 + r) * HD + d4);
                sKP[(d4+0)*AP + r] = f2tf(v.x);
                sKP[(d4+1)*AP + r] = f2tf(v.y);
                sKP[(d4+2)*AP + r] = f2tf(v.z);
                sKP[(d4+3)*AP + r] = f2tf(v.w);
            }
        }
        // V direct -> sQV[kv][d]
        {
            const int c4 = (tid & 15) << 2;
#pragma unroll
            for (int it = 0; it < 8; it++) {
                const int r = (tid >> 4) + (it << 3);
                float4 v = *(const float4*)(Vp + (size_t)(j0 + r) * HD + c4);
                sQV[r*AP + c4+0] = f2tf(v.x);
                sQV[r*AP + c4+1] = f2tf(v.y);
                sQV[r*AP + c4+2] = f2tf(v.z);
                sQV[r*AP + c4+3] = f2tf(v.w);
            }
        }
        __syncthreads();

        // S = Q K^T  (q pre-scaled)
        float s[8][4];
#pragma unroll
        for (int nt = 0; nt < 8; nt++)
#pragma unroll
            for (int i = 0; i < 4; i++) s[nt][i] = 0.f;
#pragma unroll
        for (int ks = 0; ks < 8; ks++) {
            const int kb = ks << 3;
#pragma unroll
            for (int nt = 0; nt < 8; nt++) {
                unsigned b0 = sKP[(kb+fc  )*AP + (nt<<3) + fr];
                unsigned b1 = sKP[(kb+fc+4)*AP + (nt<<3) + fr];
                mma_tf32(s[nt], qf[ks][0], qf[ks][1], qf[ks][2], qf[ks][3], b0, b1);
            }
        }

        // online softmax (rows: fr -> A, fr+8 -> B; 4 lanes per row group)
        float mxA = -1e30f, mxB = -1e30f;
#pragma unroll
        for (int nt = 0; nt < 8; nt++) {
            mxA = fmaxf(mxA, fmaxf(s[nt][0], s[nt][1]));
            mxB = fmaxf(mxB, fmaxf(s[nt][2], s[nt][3]));
        }
        mxA = fmaxf(mxA, __shfl_xor_sync(0xffffffffu, mxA, 1));
        mxA = fmaxf(mxA, __shfl_xor_sync(0xffffffffu, mxA, 2));
        mxB = fmaxf(mxB, __shfl_xor_sync(0xffffffffu, mxB, 1));
        mxB = fmaxf(mxB, __shfl_xor_sync(0xffffffffu, mxB, 2));
        const float nmA = fmaxf(mA, mxA);
        const float nmB = fmaxf(mB, mxB);
        const float sclA = __expf(mA - nmA);
        const float sclB = __expf(mB - nmB);
        float sumA = 0.f, sumB = 0.f;
#pragma unroll
        for (int nt = 0; nt < 8; nt++) {
            s[nt][0] = __expf(s[nt][0] - nmA);
            s[nt][1] = __expf(s[nt][1] - nmA);
            s[nt][2] = __expf(s[nt][2] - nmB);
            s[nt][3] = __expf(s[nt][3] - nmB);
            sumA += s[nt][0] + s[nt][1];
            sumB += s[nt][2] + s[nt][3];
        }
        sumA += __shfl_xor_sync(0xffffffffu, sumA, 1);
        sumA += __shfl_xor_sync(0xffffffffu, sumA, 2);
        sumB += __shfl_xor_sync(0xffffffffu, sumB, 1);
        sumB += __shfl_xor_sync(0xffffffffu, sumB, 2);
        lA = lA * sclA + sumA;  mA = nmA;
        lB = lB * sclB + sumB;  mB = nmB;
#pragma unroll
        for (int nt = 0; nt < 8; nt++) {
            o[nt][0] *= sclA; o[nt][1] *= sclA;
            o[nt][2] *= sclB; o[nt][3] *= sclB;
        }
        __syncthreads();   // all warps done reading K from sKP

        // write P -> sKP[kv][row] (tf32)
        {
            const int ra = (w << 4) + fr;
#pragma unroll
            for (int nt = 0; nt < 8; nt++) {
                const int kvc = (nt << 3) + (fc << 1);
                sKP[(kvc  )*AP + ra]     = f2tf(s[nt][0]);
                sKP[(kvc+1)*AP + ra]     = f2tf(s[nt][1]);
                sKP[(kvc  )*AP + ra + 8] = f2tf(s[nt][2]);
                sKP[(kvc+1)*AP + ra + 8] = f2tf(s[nt][3]);
            }
        }
        __syncthreads();   // P ready

        // O += P @ V
#pragma unroll
        for (int ks = 0; ks < 8; ks++) {
            const int kb = ks << 3;
            const int m = w << 4;
            unsigned a0 = sKP[(kb+fc  )*AP + m + fr];
            unsigned a1 = sKP[(kb+fc  )*AP + m + fr + 8];
            unsigned a2 = sKP[(kb+fc+4)*AP + m + fr];
            unsigned a3 = sKP[(kb+fc+4)*AP + m + fr + 8];
#pragma unroll
            for (int nt = 0; nt < 8; nt++) {
                unsigned b0 = sQV[(kb+fc  )*AP + (nt<<3) + fr];
                unsigned b1 = sQV[(kb+fc+4)*AP + (nt<<3) + fr];
                mma_tf32(o[nt], a0, a1, a2, a3, b0, b1);
            }
        }
    }

    // epilogue
    const float invA = 1.0f / lA;
    const float invB = 1.0f / lB;
    float* Op = Oo + (size_t)b * SS * DD + h * HD;
    const int ra = q0 + (w << 4) + fr;
#pragma unroll
    for (int nt = 0; nt < 8; nt++) {
        const int col = (nt << 3) + (fc << 1);
        *(float2*)(Op + (size_t)ra * DD + col) =
            make_float2(o[nt][0] * invA, o[nt][1] * invA);
        *(float2*)(Op + (size_t)(ra + 8) * DD + col) =
            make_float2(o[nt][2] * invB, o[nt][3] * invB);
    }
}

// ---------------- fp32 NT SGEMM (kept for out-proj precision) ---------------
__global__ __launch_bounds__(256) void sgemm_nt_bias(
    const float* __restrict__ A, const float* __restrict__ W,
    const float* __restrict__ bias, float* __restrict__ C,
    int M, int N, int K)
{
    __shared__ float As[16][128];
    __shared__ float Bs[16][128];
    const int tid = threadIdx.x;
    const int ty = tid >> 4;
    const int tx = tid & 15;
    const int bm = blockIdx.y << 7;
    const int bn = blockIdx.x << 7;
    const int lr = tid >> 2;
    const int lc = (tid & 3) << 2;

    float acc[8][8];
#pragma unroll
    for (int i = 0; i < 8; i++)
#pragma unroll
        for (int j = 0; j < 8; j++) acc[i][j] = 0.f;

    for (int k0 = 0; k0 < K; k0 += 16) {
        float4 a0 = *(const float4*)(A + (size_t)(bm + lr) * K + k0 + lc);
        float4 a1 = *(const float4*)(A + (size_t)(bm + lr + 64) * K + k0 + lc);
        float4 b0 = *(const float4*)(W + (size_t)(bn + lr) * K + k0 + lc);
        float4 b1 = *(const float4*)(W + (size_t)(bn + lr + 64) * K + k0 + lc);
        As[lc + 0][lr] = a0.x; As[lc + 1][lr] = a0.y; As[lc + 2][lr] = a0.z; As[lc + 3][lr] = a0.w;
        As[lc + 0][lr + 64] = a1.x; As[lc + 1][lr + 64] = a1.y; As[lc + 2][lr + 64] = a1.z; As[lc + 3][lr + 64] = a1.w;
        Bs[lc + 0][lr] = b0.x; Bs[lc + 1][lr] = b0.y; Bs[lc + 2][lr] = b0.z; Bs[lc + 3][lr] = b0.w;
        Bs[lc + 0][lr + 64] = b1.x; Bs[lc + 1][lr + 64] = b1.y; Bs[lc + 2][lr + 64] = b1.z; Bs[lc + 3][lr + 64] = b1.w;
        __syncthreads();
#pragma unroll
        for (int kk = 0; kk < 16; kk++) {
            float a[8], bb[8];
            *(float4*)(a)     = *(float4*)&As[kk][ty << 3];
            *(float4*)(a + 4) = *(float4*)&As[kk][(ty << 3) + 4];
            *(float4*)(bb)     = *(float4*)&Bs[kk][tx << 3];
            *(float4*)(bb + 4) = *(float4*)&Bs[kk][(tx << 3) + 4];
#pragma unroll
            for (int i = 0; i < 8; i++)
#pragma unroll
                for (int j = 0; j < 8; j++) acc[i][j] += a[i] * bb[j];
        }
        __syncthreads();
    }

#pragma unroll
    for (int i = 0; i < 8; i++) {
        int row = bm + (ty << 3) + i;
#pragma unroll
        for (int j = 0; j < 8; j++) {
            int col = bn + (tx << 3) + j;
            C[(size_t)row * N + col] = acc[i][j] + bias[col];
        }
    }
}

// ---------------- launch ----------------------------------------------------
extern "C" void kernel_launch(void* const* d_in, const int* in_sizes, int n_in,
                              void* d_out, int out_size)
{
    (void)in_sizes; (void)n_in; (void)out_size;
    const float* tokens = (const float*)d_in[0];
    const float* qkv_w  = (const float*)d_in[1];
    const float* qkv_b  = (const float*)d_in[2];
    const float* out_w  = (const float*)d_in[3];
    const float* out_b  = (const float*)d_in[4];
    float* out = (float*)d_out;

    float *qkv_s, *ao_s;
    cudaGetSymbolAddress((void**)&qkv_s, g_qkv);
    cudaGetSymbolAddress((void**)&ao_s, g_ao);

    // 1) QKV projection (tf32 tensor cores)
    gemm_tf32_nt<<<dim3(N1 / 128, M1 / 128), 256>>>(tokens, qkv_w, qkv_b, qkv_s, M1, N1, KD);
    // 2) RoPE + normalize (+SCALE on q) + split
    rope_kernel<<<(BB * HH * SS) / 4, dim3(32, 4)>>>();
    // 3) flash attention (tf32 tensor cores)
    attn_tf32<<<dim3(SS / 64, NBH), 128>>>(ao_s);
    // 4) output projection (exact fp32)
    sgemm_nt_bias<<<dim3(DD / 128, M1 / 128), 256>>>(ao_s, out_w, out_b, out, M1, DD, KD);
}

// round 3
// speedup vs baseline: 2.4939x; 1.1128x over previous
#include <cuda_runtime.h>
#include <math.h>

#define BB 2
#define SS 2048
#define DD 1024
#define HH 16
#define HD 64
#define M1 (BB*SS)      // 4096
#define N1 (3*DD)       // 3072
#define KD DD           // 1024
#define NBH (BB*HH)     // 32
#define SCALE 0.125f

// ---------------- scratch (device globals; no allocations allowed) ----------
__device__ float g_qkv[(size_t)M1 * N1];
__device__ float g_q[(size_t)NBH * SS * HD];
__device__ float g_k[(size_t)NBH * SS * HD];
__device__ float g_v[(size_t)NBH * SS * HD];
__device__ float g_ao[(size_t)BB * SS * DD];

// ---------------- tf32 helpers ----------------------------------------------
__device__ __forceinline__ unsigned f2tf(float x) {
    unsigned u;
    asm("cvt.rna.tf32.f32 %0, %1;" : "=r"(u) : "f"(x));
    return u;
}
__device__ __forceinline__ void mma_tf32(float* c,
    unsigned a0, unsigned a1, unsigned a2, unsigned a3,
    unsigned b0, unsigned b1)
{
    asm volatile(
        "mma.sync.aligned.m16n8k8.row.col.f32.tf32.tf32.f32 "
        "{%0,%1,%2,%3},{%4,%5,%6,%7},{%8,%9},{%0,%1,%2,%3};"
        : "+f"(c[0]), "+f"(c[1]), "+f"(c[2]), "+f"(c[3])
        : "r"(a0), "r"(a1), "r"(a2), "r"(a3), "r"(b0), "r"(b1));
}

// ---------------- tf32 GEMM (single-pass): C = A @ W^T + bias ---------------
#define GP 136
__global__ __launch_bounds__(256) void gemm_tf32_nt(
    const float* __restrict__ A, const float* __restrict__ W,
    const float* __restrict__ bias, float* __restrict__ C,
    int M, int N, int K)
{
    __shared__ unsigned As[2][16 * GP];
    __shared__ unsigned Bs[2][16 * GP];

    const int tid = threadIdx.x;
    const int bm = blockIdx.y << 7;
    const int bn = blockIdx.x << 7;
    const int lr  = tid >> 2;
    const int lc4 = (tid & 3) << 2;
    const int w   = tid >> 5;
    const int lane = tid & 31;
    const int wm = (w & 1) << 6;
    const int wn = (w >> 1) << 5;
    const int fr = lane >> 2;
    const int fc = lane & 3;

    float acc[4][4][4];
#pragma unroll
    for (int mt = 0; mt < 4; mt++)
#pragma unroll
        for (int nt = 0; nt < 4; nt++)
#pragma unroll
            for (int i = 0; i < 4; i++) acc[mt][nt][i] = 0.f;

    const float* Ap  = A + (size_t)(bm + lr) * K + lc4;
    const float* Ap2 = Ap + (size_t)64 * K;
    const float* Wp  = W + (size_t)(bn + lr) * K + lc4;
    const float* Wp2 = Wp + (size_t)64 * K;

    {
        float4 a0 = *(const float4*)Ap;
        float4 a1 = *(const float4*)Ap2;
        float4 b0 = *(const float4*)Wp;
        float4 b1 = *(const float4*)Wp2;
        unsigned* as = As[0]; unsigned* bs = Bs[0];
        as[(lc4+0)*GP+lr]=f2tf(a0.x); as[(lc4+1)*GP+lr]=f2tf(a0.y);
        as[(lc4+2)*GP+lr]=f2tf(a0.z); as[(lc4+3)*GP+lr]=f2tf(a0.w);
        as[(lc4+0)*GP+lr+64]=f2tf(a1.x); as[(lc4+1)*GP+lr+64]=f2tf(a1.y);
        as[(lc4+2)*GP+lr+64]=f2tf(a1.z); as[(lc4+3)*GP+lr+64]=f2tf(a1.w);
        bs[(lc4+0)*GP+lr]=f2tf(b0.x); bs[(lc4+1)*GP+lr]=f2tf(b0.y);
        bs[(lc4+2)*GP+lr]=f2tf(b0.z); bs[(lc4+3)*GP+lr]=f2tf(b0.w);
        bs[(lc4+0)*GP+lr+64]=f2tf(b1.x); bs[(lc4+1)*GP+lr+64]=f2tf(b1.y);
        bs[(lc4+2)*GP+lr+64]=f2tf(b1.z); bs[(lc4+3)*GP+lr+64]=f2tf(b1.w);
    }
    __syncthreads();

    const int nk = K >> 4;
    for (int kt = 0; kt < nk; kt++) {
        const int cur = kt & 1;
        float4 na0, na1, nb0, nb1;
        const bool more = (kt + 1 < nk);
        if (more) {
            const int off = (kt + 1) << 4;
            na0 = *(const float4*)(Ap  + off);
            na1 = *(const float4*)(Ap2 + off);
            nb0 = *(const float4*)(Wp  + off);
            nb1 = *(const float4*)(Wp2 + off);
        }
        const unsigned* as = As[cur];
        const unsigned* bs = Bs[cur];
#pragma unroll
        for (int ks = 0; ks < 2; ks++) {
            const int kb = ks << 3;
            unsigned af[4][4], bf[4][2];
#pragma unroll
            for (int mt = 0; mt < 4; mt++) {
                const int m = wm + (mt << 4);
                af[mt][0] = as[(kb+fc  )*GP + m + fr];
                af[mt][1] = as[(kb+fc  )*GP + m + fr + 8];
                af[mt][2] = as[(kb+fc+4)*GP + m + fr];
                af[mt][3] = as[(kb+fc+4)*GP + m + fr + 8];
            }
#pragma unroll
            for (int nt = 0; nt < 4; nt++) {
                const int n = wn + (nt << 3);
                bf[nt][0] = bs[(kb+fc  )*GP + n + fr];
                bf[nt][1] = bs[(kb+fc+4)*GP + n + fr];
            }
#pragma unroll
            for (int mt = 0; mt < 4; mt++)
#pragma unroll
                for (int nt = 0; nt < 4; nt++)
                    mma_tf32(acc[mt][nt], af[mt][0], af[mt][1], af[mt][2], af[mt][3],
                             bf[nt][0], bf[nt][1]);
        }
        if (more) {
            unsigned* asn = As[cur ^ 1]; unsigned* bsn = Bs[cur ^ 1];
            asn[(lc4+0)*GP+lr]=f2tf(na0.x); asn[(lc4+1)*GP+lr]=f2tf(na0.y);
            asn[(lc4+2)*GP+lr]=f2tf(na0.z); asn[(lc4+3)*GP+lr]=f2tf(na0.w);
            asn[(lc4+0)*GP+lr+64]=f2tf(na1.x); asn[(lc4+1)*GP+lr+64]=f2tf(na1.y);
            asn[(lc4+2)*GP+lr+64]=f2tf(na1.z); asn[(lc4+3)*GP+lr+64]=f2tf(na1.w);
            bsn[(lc4+0)*GP+lr]=f2tf(nb0.x); bsn[(lc4+1)*GP+lr]=f2tf(nb0.y);
            bsn[(lc4+2)*GP+lr]=f2tf(nb0.z); bsn[(lc4+3)*GP+lr]=f2tf(nb0.w);
            bsn[(lc4+0)*GP+lr+64]=f2tf(nb1.x); bsn[(lc4+1)*GP+lr+64]=f2tf(nb1.y);
            bsn[(lc4+2)*GP+lr+64]=f2tf(nb1.z); bsn[(lc4+3)*GP+lr+64]=f2tf(nb1.w);
        }
        __syncthreads();
    }

#pragma unroll
    for (int mt = 0; mt < 4; mt++) {
        const int row = bm + wm + (mt << 4) + fr;
#pragma unroll
        for (int nt = 0; nt < 4; nt++) {
            const int col = bn + wn + (nt << 3) + (fc << 1);
            *(float2*)(C + (size_t)row * N + col) =
                make_float2(acc[mt][nt][0] + bias[col], acc[mt][nt][1] + bias[col + 1]);
            *(float2*)(C + (size_t)(row + 8) * N + col) =
                make_float2(acc[mt][nt][2] + bias[col], acc[mt][nt][3] + bias[col + 1]);
        }
    }
}

// ---------------- split-tf32 GEMM (fp32-accurate): C = A @ W^T + bias -------
// x = hi + lo (tf32 each); C ~= ah*bh + al*bh + ah*bl. BK=8, single buffer.
__global__ __launch_bounds__(256) void gemm_tf32x2_nt(
    const float* __restrict__ A, const float* __restrict__ W,
    const float* __restrict__ bias, float* __restrict__ C,
    int M, int N, int K)
{
    __shared__ unsigned Ah[8 * GP], Al[8 * GP], Bh[8 * GP], Bl[8 * GP];

    const int tid = threadIdx.x;
    const int bm = blockIdx.y << 7;
    const int bn = blockIdx.x << 7;
    const int lr = tid >> 1;           // 0..127
    const int lc = (tid & 1) << 2;     // 0 or 4
    const int w = tid >> 5;
    const int lane = tid & 31;
    const int wm = (w & 1) << 6;
    const int wn = (w >> 1) << 5;
    const int fr = lane >> 2;
    const int fc = lane & 3;

    float acc[4][4][4];
#pragma unroll
    for (int mt = 0; mt < 4; mt++)
#pragma unroll
        for (int nt = 0; nt < 4; nt++)
#pragma unroll
            for (int i = 0; i < 4; i++) acc[mt][nt][i] = 0.f;

    const float* Ap = A + (size_t)(bm + lr) * K + lc;
    const float* Wp = W + (size_t)(bn + lr) * K + lc;

    for (int k0 = 0; k0 < K; k0 += 8) {
        float4 a = *(const float4*)(Ap + k0);
        float4 b = *(const float4*)(Wp + k0);
        const float av[4] = {a.x, a.y, a.z, a.w};
        const float bv[4] = {b.x, b.y, b.z, b.w};
#pragma unroll
        for (int j = 0; j < 4; j++) {
            unsigned h = f2tf(av[j]);
            unsigned l = f2tf(av[j] - __uint_as_float(h));
            Ah[(lc + j) * GP + lr] = h;
            Al[(lc + j) * GP + lr] = l;
            unsigned hb = f2tf(bv[j]);
            unsigned lb = f2tf(bv[j] - __uint_as_float(hb));
            Bh[(lc + j) * GP + lr] = hb;
            Bl[(lc + j) * GP + lr] = lb;
        }
        __syncthreads();

        unsigned ah[4][4], al[4][4], bh[4][2], bl[4][2];
#pragma unroll
        for (int mt = 0; mt < 4; mt++) {
            const int m = wm + (mt << 4);
            ah[mt][0] = Ah[(fc  )*GP + m + fr];
            ah[mt][1] = Ah[(fc  )*GP + m + fr + 8];
            ah[mt][2] = Ah[(fc+4)*GP + m + fr];
            ah[mt][3] = Ah[(fc+4)*GP + m + fr + 8];
            al[mt][0] = Al[(fc  )*GP + m + fr];
            al[mt][1] = Al[(fc  )*GP + m + fr + 8];
            al[mt][2] = Al[(fc+4)*GP + m + fr];
            al[mt][3] = Al[(fc+4)*GP + m + fr + 8];
        }
#pragma unroll
        for (int nt = 0; nt < 4; nt++) {
            const int n = wn + (nt << 3);
            bh[nt][0] = Bh[(fc  )*GP + n + fr];
            bh[nt][1] = Bh[(fc+4)*GP + n + fr];
            bl[nt][0] = Bl[(fc  )*GP + n + fr];
            bl[nt][1] = Bl[(fc+4)*GP + n + fr];
        }
#pragma unroll
        for (int mt = 0; mt < 4; mt++)
#pragma unroll
            for (int nt = 0; nt < 4; nt++) {
                mma_tf32(acc[mt][nt], al[mt][0], al[mt][1], al[mt][2], al[mt][3],
                         bh[nt][0], bh[nt][1]);
                mma_tf32(acc[mt][nt], ah[mt][0], ah[mt][1], ah[mt][2], ah[mt][3],
                         bl[nt][0], bl[nt][1]);
                mma_tf32(acc[mt][nt], ah[mt][0], ah[mt][1], ah[mt][2], ah[mt][3],
                         bh[nt][0], bh[nt][1]);
            }
        __syncthreads();
    }

#pragma unroll
    for (int mt = 0; mt < 4; mt++) {
        const int row = bm + wm + (mt << 4) + fr;
#pragma unroll
        for (int nt = 0; nt < 4; nt++) {
            const int col = bn + wn + (nt << 3) + (fc << 1);
            *(float2*)(C + (size_t)row * N + col) =
                make_float2(acc[mt][nt][0] + bias[col], acc[mt][nt][1] + bias[col + 1]);
            *(float2*)(C + (size_t)(row + 8) * N + col) =
                make_float2(acc[mt][nt][2] + bias[col], acc[mt][nt][3] + bias[col + 1]);
        }
    }
}

// ---------------- RoPE + L2-normalize + scatter to [B,H,S,HD] ---------------
__global__ __launch_bounds__(128) void rope_kernel()
{
    const int f = threadIdx.x;
    const int rid = blockIdx.x * 4 + threadIdx.y;
    const int bh = rid >> 11;
    const int s  = rid & (SS - 1);
    const int b  = bh >> 4;
    const int h  = bh & 15;

    double invd = exp(-(double)f * (9.210340371976184 / 32.0));
    float theta = (float)((double)s * invd);
    float sn, cs;
    sincosf(theta, &sn, &cs);

    const float* src = g_qkv + (size_t)(b * SS + s) * N1 + h * HD;
    const size_t dst = ((size_t)bh * SS + s) * HD;

    {
        float e = src[2 * f], o = src[2 * f + 1];
        float re = e * cs - o * sn;
        float ro = e * sn + o * cs;
        float sq = re * re + ro * ro;
#pragma unroll
        for (int msk = 16; msk > 0; msk >>= 1) sq += __shfl_xor_sync(0xffffffffu, sq, msk);
        float inv = SCALE / fmaxf(sqrtf(sq), 1e-12f);
        g_q[dst + 2 * f] = re * inv;
        g_q[dst + 2 * f + 1] = ro * inv;
    }
    {
        float e = src[DD + 2 * f], o = src[DD + 2 * f + 1];
        float re = e * cs - o * sn;
        float ro = e * sn + o * cs;
        float sq = re * re + ro * ro;
#pragma unroll
        for (int msk = 16; msk > 0; msk >>= 1) sq += __shfl_xor_sync(0xffffffffu, sq, msk);
        float inv = 1.0f / fmaxf(sqrtf(sq), 1e-12f);
        g_k[dst + 2 * f] = re * inv;
        g_k[dst + 2 * f + 1] = ro * inv;
    }
    g_v[dst + 2 * f] = src[2 * DD + 2 * f];
    g_v[dst + 2 * f + 1] = src[2 * DD + 2 * f + 1];
}

// ---------------- tf32 flash attention, BM=128, 8 warps ---------------------
// dynamic smem: sK[64][72], sV[64][72], sP[64][136] (sP doubles as Q staging)
#define AP 72
#define PP 136
#define ATTN_SMEM ((4608 + 4608 + 8704) * 4)
__global__ __launch_bounds__(256) void attn_tf32(float* __restrict__ Oo)
{
    extern __shared__ unsigned smem[];
    unsigned* sK = smem;
    unsigned* sV = smem + 4608;
    unsigned* sP = smem + 9216;

    const int tid = threadIdx.x;
    const int w = tid >> 5;
    const int lane = tid & 31;
    const int fr = lane >> 2;
    const int fc = lane & 3;
    const int bh = blockIdx.y;
    const int b = bh >> 4, h = bh & 15;
    const int q0 = blockIdx.x << 7;

    const float* Qp = g_q + (size_t)bh * SS * HD;
    const float* Kp = g_k + (size_t)bh * SS * HD;
    const float* Vp = g_v + (size_t)bh * SS * HD;

    // stage Q transposed into sP: sP[d][row], rows 0..127
#pragma unroll
    for (int it = 0; it < 2; it++) {
        const int d4 = (w + (it << 3)) << 2;
#pragma unroll
        for (int h2 = 0; h2 < 4; h2++) {
            const int r = lane + (h2 << 5);
            float4 v = *(const float4*)(Qp + (size_t)(q0 + r) * HD + d4);
            sP[(d4+0)*PP + r] = f2tf(v.x);
            sP[(d4+1)*PP + r] = f2tf(v.y);
            sP[(d4+2)*PP + r] = f2tf(v.z);
            sP[(d4+3)*PP + r] = f2tf(v.w);
        }
    }
    __syncthreads();

    // extract Q fragments
    unsigned qf[8][4];
    {
        const int m = w << 4;
#pragma unroll
        for (int ks = 0; ks < 8; ks++) {
            const int kb = ks << 3;
            qf[ks][0] = sP[(kb+fc  )*PP + m + fr];
            qf[ks][1] = sP[(kb+fc  )*PP + m + fr + 8];
            qf[ks][2] = sP[(kb+fc+4)*PP + m + fr];
            qf[ks][3] = sP[(kb+fc+4)*PP + m + fr + 8];
        }
    }

    float o[8][4];
#pragma unroll
    for (int nt = 0; nt < 8; nt++)
#pragma unroll
        for (int i = 0; i < 4; i++) o[nt][i] = 0.f;
    float mA = -1e30f, mB = -1e30f, lA = 0.f, lB = 0.f;

    for (int j0 = 0; j0 < SS; j0 += 64) {
        __syncthreads();   // previous tile's sK/sV reads done; Q extraction done

        // K transposed -> sK[d][kv]
#pragma unroll
        for (int it = 0; it < 2; it++) {
            const int d4 = (w + (it << 3)) << 2;
#pragma unroll
            for (int h2 = 0; h2 < 2; h2++) {
                const int r = lane + (h2 << 5);
                float4 v = *(const float4*)(Kp + (size_t)(j0 + r) * HD + d4);
                sK[(d4+0)*AP + r] = f2tf(v.x);
                sK[(d4+1)*AP + r] = f2tf(v.y);
                sK[(d4+2)*AP + r] = f2tf(v.z);
                sK[(d4+3)*AP + r] = f2tf(v.w);
            }
        }
        // V direct -> sV[kv][d]
        {
            const int c4 = (tid & 15) << 2;
#pragma unroll
            for (int it = 0; it < 4; it++) {
                const int r = (tid >> 4) + (it << 4);
                float4 v = *(const float4*)(Vp + (size_t)(j0 + r) * HD + c4);
                sV[r*AP + c4+0] = f2tf(v.x);
                sV[r*AP + c4+1] = f2tf(v.y);
                sV[r*AP + c4+2] = f2tf(v.z);
                sV[r*AP + c4+3] = f2tf(v.w);
            }
        }
        __syncthreads();

        // S = Q K^T
        float s[8][4];
#pragma unroll
        for (int nt = 0; nt < 8; nt++)
#pragma unroll
            for (int i = 0; i < 4; i++) s[nt][i] = 0.f;
#pragma unroll
        for (int ks = 0; ks < 8; ks++) {
            const int kb = ks << 3;
#pragma unroll
            for (int nt = 0; nt < 8; nt++) {
                unsigned b0 = sK[(kb+fc  )*AP + (nt<<3) + fr];
                unsigned b1 = sK[(kb+fc+4)*AP + (nt<<3) + fr];
                mma_tf32(s[nt], qf[ks][0], qf[ks][1], qf[ks][2], qf[ks][3], b0, b1);
            }
        }

        // online softmax
        float mxA = -1e30f, mxB = -1e30f;
#pragma unroll
        for (int nt = 0; nt < 8; nt++) {
            mxA = fmaxf(mxA, fmaxf(s[nt][0], s[nt][1]));
            mxB = fmaxf(mxB, fmaxf(s[nt][2], s[nt][3]));
        }
        mxA = fmaxf(mxA, __shfl_xor_sync(0xffffffffu, mxA, 1));
        mxA = fmaxf(mxA, __shfl_xor_sync(0xffffffffu, mxA, 2));
        mxB = fmaxf(mxB, __shfl_xor_sync(0xffffffffu, mxB, 1));
        mxB = fmaxf(mxB, __shfl_xor_sync(0xffffffffu, mxB, 2));
        const float nmA = fmaxf(mA, mxA);
        const float nmB = fmaxf(mB, mxB);
        const float sclA = __expf(mA - nmA);
        const float sclB = __expf(mB - nmB);
        float sumA = 0.f, sumB = 0.f;
#pragma unroll
        for (int nt = 0; nt < 8; nt++) {
            s[nt][0] = __expf(s[nt][0] - nmA);
            s[nt][1] = __expf(s[nt][1] - nmA);
            s[nt][2] = __expf(s[nt][2] - nmB);
            s[nt][3] = __expf(s[nt][3] - nmB);
            sumA += s[nt][0] + s[nt][1];
            sumB += s[nt][2] + s[nt][3];
        }
        sumA += __shfl_xor_sync(0xffffffffu, sumA, 1);
        sumA += __shfl_xor_sync(0xffffffffu, sumA, 2);
        sumB += __shfl_xor_sync(0xffffffffu, sumB, 1);
        sumB += __shfl_xor_sync(0xffffffffu, sumB, 2);
        lA = lA * sclA + sumA;  mA = nmA;
        lB = lB * sclB + sumB;  mB = nmB;
#pragma unroll
        for (int nt = 0; nt < 8; nt++) {
            o[nt][0] *= sclA; o[nt][1] *= sclA;
            o[nt][2] *= sclB; o[nt][3] *= sclB;
        }

        // write P -> sP[kv][row] (warp-private rows)
        {
            const int ra = (w << 4) + fr;
#pragma unroll
            for (int nt = 0; nt < 8; nt++) {
                const int kvc = (nt << 3) + (fc << 1);
                sP[(kvc  )*PP + ra]     = f2tf(s[nt][0]);
                sP[(kvc+1)*PP + ra]     = f2tf(s[nt][1]);
                sP[(kvc  )*PP + ra + 8] = f2tf(s[nt][2]);
                sP[(kvc+1)*PP + ra + 8] = f2tf(s[nt][3]);
            }
        }
        __syncwarp();

        // O += P @ V
#pragma unroll
        for (int ks = 0; ks < 8; ks++) {
            const int kb = ks << 3;
            const int m = w << 4;
            unsigned a0 = sP[(kb+fc  )*PP + m + fr];
            unsigned a1 = sP[(kb+fc  )*PP + m + fr + 8];
            unsigned a2 = sP[(kb+fc+4)*PP + m + fr];
            unsigned a3 = sP[(kb+fc+4)*PP + m + fr + 8];
#pragma unroll
            for (int nt = 0; nt < 8; nt++) {
                unsigned b0 = sV[(kb+fc  )*AP + (nt<<3) + fr];
                unsigned b1 = sV[(kb+fc+4)*AP + (nt<<3) + fr];
                mma_tf32(o[nt], a0, a1, a2, a3, b0, b1);
            }
        }
    }

    // epilogue
    const float invA = 1.0f / lA;
    const float invB = 1.0f / lB;
    float* Op = Oo + (size_t)b * SS * DD + h * HD;
    const int ra = q0 + (w << 4) + fr;
#pragma unroll
    for (int nt = 0; nt < 8; nt++) {
        const int col = (nt << 3) + (fc << 1);
        *(float2*)(Op + (size_t)ra * DD + col) =
            make_float2(o[nt][0] * invA, o[nt][1] * invA);
        *(float2*)(Op + (size_t)(ra + 8) * DD + col) =
            make_float2(o[nt][2] * invB, o[nt][3] * invB);
    }
}

// ---------------- launch ----------------------------------------------------
extern "C" void kernel_launch(void* const* d_in, const int* in_sizes, int n_in,
                              void* d_out, int out_size)
{
    (void)in_sizes; (void)n_in; (void)out_size;
    const float* tokens = (const float*)d_in[0];
    const float* qkv_w  = (const float*)d_in[1];
    const float* qkv_b  = (const float*)d_in[2];
    const float* out_w  = (const float*)d_in[3];
    const float* out_b  = (const float*)d_in[4];
    float* out = (float*)d_out;

    float *qkv_s, *ao_s;
    cudaGetSymbolAddress((void**)&qkv_s, g_qkv);
    cudaGetSymbolAddress((void**)&ao_s, g_ao);

    static int smem_set = 0;
    if (!smem_set) {
        cudaFuncSetAttribute(attn_tf32, cudaFuncAttributeMaxDynamicSharedMemorySize, ATTN_SMEM);
        smem_set = 1;
    }

    // 1) QKV projection (tf32)
    gemm_tf32_nt<<<dim3(N1 / 128, M1 / 128), 256>>>(tokens, qkv_w, qkv_b, qkv_s, M1, N1, KD);
    // 2) RoPE + normalize (+SCALE on q) + split
    rope_kernel<<<(BB * HH * SS) / 4, dim3(32, 4)>>>();
    // 3) flash attention (tf32, BM=128)
    attn_tf32<<<dim3(SS / 128, NBH), 256, ATTN_SMEM>>>(ao_s);
    // 4) output projection (split-tf32, fp32-accurate)
    gemm_tf32x2_nt<<<dim3(DD / 128, M1 / 128), 256>>>(ao_s, out_w, out_b, out, M1, DD, KD);
}

// round 4
// speedup vs baseline: 2.8334x; 1.1361x over previous
#include <cuda_runtime.h>
#include <math.h>

#define BB 2
#define SS 2048
#define DD 1024
#define HH 16
#define HD 64
#define M1 (BB*SS)      // 4096
#define N1 (3*DD)       // 3072
#define KD DD           // 1024
#define NBH (BB*HH)     // 32
#define SCALE 0.125f

// ---------------- scratch (device globals; no allocations allowed) ----------
__device__ float g_qkv[(size_t)M1 * N1];
__device__ float g_q[(size_t)NBH * SS * HD];
__device__ float g_k[(size_t)NBH * SS * HD];
__device__ float g_v[(size_t)NBH * SS * HD];
__device__ float g_ao[(size_t)BB * SS * DD];

// ---------------- helpers ----------------------------------------------------
__device__ __forceinline__ unsigned f2tf(float x) {
    unsigned u;
    asm("cvt.rna.tf32.f32 %0, %1;" : "=r"(u) : "f"(x));
    return u;
}
__device__ __forceinline__ void mma_tf32(float* c,
    unsigned a0, unsigned a1, unsigned a2, unsigned a3,
    unsigned b0, unsigned b1)
{
    asm volatile(
        "mma.sync.aligned.m16n8k8.row.col.f32.tf32.tf32.f32 "
        "{%0,%1,%2,%3},{%4,%5,%6,%7},{%8,%9},{%0,%1,%2,%3};"
        : "+f"(c[0]), "+f"(c[1]), "+f"(c[2]), "+f"(c[3])
        : "r"(a0), "r"(a1), "r"(a2), "r"(a3), "r"(b0), "r"(b1));
}
__device__ __forceinline__ void cp16(unsigned s, const void* g) {
    asm volatile("cp.async.cg.shared.global [%0], [%1], 16;" :: "r"(s), "l"(g));
}
__device__ __forceinline__ void cp_commit() {
    asm volatile("cp.async.commit_group;");
}
template<int N> __device__ __forceinline__ void cp_wait() {
    asm volatile("cp.async.wait_group %0;" :: "n"(N));
}

// ---------------- tf32 GEMM: C[M,N] = A[M,K] @ W[N,K]^T + bias --------------
#define GP 136
__global__ __launch_bounds__(256) void gemm_tf32_nt(
    const float* __restrict__ A, const float* __restrict__ W,
    const float* __restrict__ bias, float* __restrict__ C,
    int M, int N, int K)
{
    __shared__ unsigned As[2][16 * GP];
    __shared__ unsigned Bs[2][16 * GP];

    const int tid = threadIdx.x;
    const int bm = blockIdx.y << 7;
    const int bn = blockIdx.x << 7;
    const int lr  = tid >> 2;
    const int lc4 = (tid & 3) << 2;
    const int w   = tid >> 5;
    const int lane = tid & 31;
    const int wm = (w & 1) << 6;
    const int wn = (w >> 1) << 5;
    const int fr = lane >> 2;
    const int fc = lane & 3;

    float acc[4][4][4];
#pragma unroll
    for (int mt = 0; mt < 4; mt++)
#pragma unroll
        for (int nt = 0; nt < 4; nt++)
#pragma unroll
            for (int i = 0; i < 4; i++) acc[mt][nt][i] = 0.f;

    const float* Ap  = A + (size_t)(bm + lr) * K + lc4;
    const float* Ap2 = Ap + (size_t)64 * K;
    const float* Wp  = W + (size_t)(bn + lr) * K + lc4;
    const float* Wp2 = Wp + (size_t)64 * K;

    {
        float4 a0 = *(const float4*)Ap;
        float4 a1 = *(const float4*)Ap2;
        float4 b0 = *(const float4*)Wp;
        float4 b1 = *(const float4*)Wp2;
        unsigned* as = As[0]; unsigned* bs = Bs[0];
        as[(lc4+0)*GP+lr]=f2tf(a0.x); as[(lc4+1)*GP+lr]=f2tf(a0.y);
        as[(lc4+2)*GP+lr]=f2tf(a0.z); as[(lc4+3)*GP+lr]=f2tf(a0.w);
        as[(lc4+0)*GP+lr+64]=f2tf(a1.x); as[(lc4+1)*GP+lr+64]=f2tf(a1.y);
        as[(lc4+2)*GP+lr+64]=f2tf(a1.z); as[(lc4+3)*GP+lr+64]=f2tf(a1.w);
        bs[(lc4+0)*GP+lr]=f2tf(b0.x); bs[(lc4+1)*GP+lr]=f2tf(b0.y);
        bs[(lc4+2)*GP+lr]=f2tf(b0.z); bs[(lc4+3)*GP+lr]=f2tf(b0.w);
        bs[(lc4+0)*GP+lr+64]=f2tf(b1.x); bs[(lc4+1)*GP+lr+64]=f2tf(b1.y);
        bs[(lc4+2)*GP+lr+64]=f2tf(b1.z); bs[(lc4+3)*GP+lr+64]=f2tf(b1.w);
    }
    __syncthreads();

    const int nk = K >> 4;
    for (int kt = 0; kt < nk; kt++) {
        const int cur = kt & 1;
        float4 na0, na1, nb0, nb1;
        const bool more = (kt + 1 < nk);
        if (more) {
            const int off = (kt + 1) << 4;
            na0 = *(const float4*)(Ap  + off);
            na1 = *(const float4*)(Ap2 + off);
            nb0 = *(const float4*)(Wp  + off);
            nb1 = *(const float4*)(Wp2 + off);
        }
        const unsigned* as = As[cur];
        const unsigned* bs = Bs[cur];
#pragma unroll
        for (int ks = 0; ks < 2; ks++) {
            const int kb = ks << 3;
            unsigned af[4][4], bf[4][2];
#pragma unroll
            for (int mt = 0; mt < 4; mt++) {
                const int m = wm + (mt << 4);
                af[mt][0] = as[(kb+fc  )*GP + m + fr];
                af[mt][1] = as[(kb+fc  )*GP + m + fr + 8];
                af[mt][2] = as[(kb+fc+4)*GP + m + fr];
                af[mt][3] = as[(kb+fc+4)*GP + m + fr + 8];
            }
#pragma unroll
            for (int nt = 0; nt < 4; nt++) {
                const int n = wn + (nt << 3);
                bf[nt][0] = bs[(kb+fc  )*GP + n + fr];
                bf[nt][1] = bs[(kb+fc+4)*GP + n + fr];
            }
#pragma unroll
            for (int mt = 0; mt < 4; mt++)
#pragma unroll
                for (int nt = 0; nt < 4; nt++)
                    mma_tf32(acc[mt][nt], af[mt][0], af[mt][1], af[mt][2], af[mt][3],
                             bf[nt][0], bf[nt][1]);
        }
        if (more) {
            unsigned* asn = As[cur ^ 1]; unsigned* bsn = Bs[cur ^ 1];
            asn[(lc4+0)*GP+lr]=f2tf(na0.x); asn[(lc4+1)*GP+lr]=f2tf(na0.y);
            asn[(lc4+2)*GP+lr]=f2tf(na0.z); asn[(lc4+3)*GP+lr]=f2tf(na0.w);
            asn[(lc4+0)*GP+lr+64]=f2tf(na1.x); asn[(lc4+1)*GP+lr+64]=f2tf(na1.y);
            asn[(lc4+2)*GP+lr+64]=f2tf(na1.z); asn[(lc4+3)*GP+lr+64]=f2tf(na1.w);
            bsn[(lc4+0)*GP+lr]=f2tf(nb0.x); bsn[(lc4+1)*GP+lr]=f2tf(nb0.y);
            bsn[(lc4+2)*GP+lr]=f2tf(nb0.z); bsn[(lc4+3)*GP+lr]=f2tf(nb0.w);
            bsn[(lc4+0)*GP+lr+64]=f2tf(nb1.x); bsn[(lc4+1)*GP+lr+64]=f2tf(nb1.y);
            bsn[(lc4+2)*GP+lr+64]=f2tf(nb1.z); bsn[(lc4+3)*GP+lr+64]=f2tf(nb1.w);
        }
        __syncthreads();
    }

#pragma unroll
    for (int mt = 0; mt < 4; mt++) {
        const int row = bm + wm + (mt << 4) + fr;
#pragma unroll
        for (int nt = 0; nt < 4; nt++) {
            const int col = bn + wn + (nt << 3) + (fc << 1);
            *(float2*)(C + (size_t)row * N + col) =
                make_float2(acc[mt][nt][0] + bias[col], acc[mt][nt][1] + bias[col + 1]);
            *(float2*)(C + (size_t)(row + 8) * N + col) =
                make_float2(acc[mt][nt][2] + bias[col], acc[mt][nt][3] + bias[col + 1]);
        }
    }
}

// ---------------- RoPE + L2-normalize + scatter to [B,H,S,HD] ---------------
__global__ __launch_bounds__(128) void rope_kernel()
{
    const int f = threadIdx.x;
    const int rid = blockIdx.x * 4 + threadIdx.y;
    const int bh = rid >> 11;
    const int s  = rid & (SS - 1);
    const int b  = bh >> 4;
    const int h  = bh & 15;

    double invd = exp(-(double)f * (9.210340371976184 / 32.0));
    float theta = (float)((double)s * invd);
    float sn, cs;
    sincosf(theta, &sn, &cs);

    const float* src = g_qkv + (size_t)(b * SS + s) * N1 + h * HD;
    const size_t dst = ((size_t)bh * SS + s) * HD;

    {
        float e = src[2 * f], o = src[2 * f + 1];
        float re = e * cs - o * sn;
        float ro = e * sn + o * cs;
        float sq = re * re + ro * ro;
#pragma unroll
        for (int msk = 16; msk > 0; msk >>= 1) sq += __shfl_xor_sync(0xffffffffu, sq, msk);
        float inv = SCALE / fmaxf(sqrtf(sq), 1e-12f);
        g_q[dst + 2 * f] = re * inv;
        g_q[dst + 2 * f + 1] = ro * inv;
    }
    {
        float e = src[DD + 2 * f], o = src[DD + 2 * f + 1];
        float re = e * cs - o * sn;
        float ro = e * sn + o * cs;
        float sq = re * re + ro * ro;
#pragma unroll
        for (int msk = 16; msk > 0; msk >>= 1) sq += __shfl_xor_sync(0xffffffffu, sq, msk);
        float inv = 1.0f / fmaxf(sqrtf(sq), 1e-12f);
        g_k[dst + 2 * f] = re * inv;
        g_k[dst + 2 * f + 1] = ro * inv;
    }
    g_v[dst + 2 * f] = src[2 * DD + 2 * f];
    g_v[dst + 2 * f + 1] = src[2 * DD + 2 * f + 1];
}

// ---------------- tf32 flash attention, BM=128, cp.async pipeline -----------
// K tiles: raw fp32, row-major [kv][d], pitch 68 (S-phase reads conflict-free)
// V tiles: raw fp32, row-major [kv][d], pitch 72 (PV-phase reads conflict-free)
// 3 buffers each, prefetch depth 2, one __syncthreads per kv tile.
#define KP_ 68
#define VP_ 72
#define PP 136
#define KBUF (64*KP_)    // 4352 words
#define VBUF (64*VP_)    // 4608 words
#define ATTN_SMEM ((3*KBUF + 3*VBUF + 64*PP) * 4)   // 142336 bytes

__global__ __launch_bounds__(256) void attn_tf32(float* __restrict__ Oo)
{
    extern __shared__ float fsm[];
    float* sK = fsm;                         // 3 x KBUF
    float* sV = fsm + 3 * KBUF;              // 3 x VBUF
    unsigned* sP = (unsigned*)(fsm + 3 * KBUF + 3 * VBUF);   // 64 x PP

    const int tid = threadIdx.x;
    const int w = tid >> 5;
    const int lane = tid & 31;
    const int fr = lane >> 2;
    const int fc = lane & 3;
    const int bh = blockIdx.y;
    const int b = bh >> 4, h = bh & 15;
    const int q0 = blockIdx.x << 7;

    const float* Qp = g_q + (size_t)bh * SS * HD;
    const float* Kp = g_k + (size_t)bh * SS * HD;
    const float* Vp = g_v + (size_t)bh * SS * HD;

    const unsigned smem_u = (unsigned)__cvta_generic_to_shared(fsm);
    const unsigned sK_u = smem_u;
    const unsigned sV_u = smem_u + 3 * KBUF * 4;

    // per-thread cp.async coordinates (4 chunks of 16B per tile per tensor)
    const int ldrow0 = tid >> 4;          // 0..15
    const int ldc4   = (tid & 15) << 2;   // 0,4,...,60

    auto issue_tile = [&](int jt) {
        const int bi = jt % 3;
        const float* gK = Kp + ((size_t)jt << 6) * HD;
        const float* gV = Vp + ((size_t)jt << 6) * HD;
        const unsigned kb_ = sK_u + bi * KBUF * 4;
        const unsigned vb_ = sV_u + bi * VBUF * 4;
#pragma unroll
        for (int t = 0; t < 4; t++) {
            const int row = ldrow0 + (t << 4);
            cp16(kb_ + (row * KP_ + ldc4) * 4, gK + row * HD + ldc4);
            cp16(vb_ + (row * VP_ + ldc4) * 4, gV + row * HD + ldc4);
        }
        cp_commit();
    };

    // start fetching tiles 0 and 1 immediately
    issue_tile(0);
    issue_tile(1);

    // stage Q transposed into sP: sP[d][row]
#pragma unroll
    for (int it = 0; it < 2; it++) {
        const int d4 = (w + (it << 3)) << 2;
#pragma unroll
        for (int h2 = 0; h2 < 4; h2++) {
            const int r = lane + (h2 << 5);
            float4 v = *(const float4*)(Qp + (size_t)(q0 + r) * HD + d4);
            sP[(d4+0)*PP + r] = f2tf(v.x);
            sP[(d4+1)*PP + r] = f2tf(v.y);
            sP[(d4+2)*PP + r] = f2tf(v.z);
            sP[(d4+3)*PP + r] = f2tf(v.w);
        }
    }
    __syncthreads();

    // extract Q fragments (registers for whole kernel)
    unsigned qf[8][4];
    {
        const int m = w << 4;
#pragma unroll
        for (int ks = 0; ks < 8; ks++) {
            const int kb = ks << 3;
            qf[ks][0] = sP[(kb+fc  )*PP + m + fr];
            qf[ks][1] = sP[(kb+fc  )*PP + m + fr + 8];
            qf[ks][2] = sP[(kb+fc+4)*PP + m + fr];
            qf[ks][3] = sP[(kb+fc+4)*PP + m + fr + 8];
        }
    }

    float o[8][4];
#pragma unroll
    for (int nt = 0; nt < 8; nt++)
#pragma unroll
        for (int i = 0; i < 4; i++) o[nt][i] = 0.f;
    float mA = -1e30f, mB = -1e30f, lA = 0.f, lB = 0.f;

    const int NT = SS / 64;   // 32
    for (int jt = 0; jt < NT; jt++) {
        // prefetch tile jt+2 into buffer (jt+2)%3 (last read at tile jt-1,
        // protected by the __syncthreads below of iteration jt-1 ... jt)
        if (jt + 2 < NT) { issue_tile(jt + 2); cp_wait<2>(); }
        else if (jt + 1 < NT) { cp_wait<1>(); }
        else { cp_wait<0>(); }
        __syncthreads();     // tile jt visible to all; prev compute done

        const float* Kt = sK + (jt % 3) * KBUF;
        const float* Vt = sV + (jt % 3) * VBUF;

        // S = Q K^T (B-fragments: K[kv][d] read transposed, cvt at use)
        float s[8][4];
#pragma unroll
        for (int nt = 0; nt < 8; nt++)
#pragma unroll
            for (int i = 0; i < 4; i++) s[nt][i] = 0.f;
#pragma unroll
        for (int ks = 0; ks < 8; ks++) {
            const int kb = ks << 3;
#pragma unroll
            for (int nt = 0; nt < 8; nt++) {
                const int kv = (nt << 3) + fr;
                unsigned b0 = f2tf(Kt[kv * KP_ + kb + fc]);
                unsigned b1 = f2tf(Kt[kv * KP_ + kb + fc + 4]);
                mma_tf32(s[nt], qf[ks][0], qf[ks][1], qf[ks][2], qf[ks][3], b0, b1);
            }
        }

        // online softmax
        float mxA = -1e30f, mxB = -1e30f;
#pragma unroll
        for (int nt = 0; nt < 8; nt++) {
            mxA = fmaxf(mxA, fmaxf(s[nt][0], s[nt][1]));
            mxB = fmaxf(mxB, fmaxf(s[nt][2], s[nt][3]));
        }
        mxA = fmaxf(mxA, __shfl_xor_sync(0xffffffffu, mxA, 1));
        mxA = fmaxf(mxA, __shfl_xor_sync(0xffffffffu, mxA, 2));
        mxB = fmaxf(mxB, __shfl_xor_sync(0xffffffffu, mxB, 1));
        mxB = fmaxf(mxB, __shfl_xor_sync(0xffffffffu, mxB, 2));
        const float nmA = fmaxf(mA, mxA);
        const float nmB = fmaxf(mB, mxB);
        const float sclA = __expf(mA - nmA);
        const float sclB = __expf(mB - nmB);
        float sumA = 0.f, sumB = 0.f;
#pragma unroll
        for (int nt = 0; nt < 8; nt++) {
            s[nt][0] = __expf(s[nt][0] - nmA);
            s[nt][1] = __expf(s[nt][1] - nmA);
            s[nt][2] = __expf(s[nt][2] - nmB);
            s[nt][3] = __expf(s[nt][3] - nmB);
            sumA += s[nt][0] + s[nt][1];
            sumB += s[nt][2] + s[nt][3];
        }
        sumA += __shfl_xor_sync(0xffffffffu, sumA, 1);
        sumA += __shfl_xor_sync(0xffffffffu, sumA, 2);
        sumB += __shfl_xor_sync(0xffffffffu, sumB, 1);
        sumB += __shfl_xor_sync(0xffffffffu, sumB, 2);
        lA = lA * sclA + sumA;  mA = nmA;
        lB = lB * sclB + sumB;  mB = nmB;
#pragma unroll
        for (int nt = 0; nt < 8; nt++) {
            o[nt][0] *= sclA; o[nt][1] *= sclA;
            o[nt][2] *= sclB; o[nt][3] *= sclB;
        }

        // write P -> sP[kv][row] (warp-private rows)
        __syncwarp();
        {
            const int ra = (w << 4) + fr;
#pragma unroll
            for (int nt = 0; nt < 8; nt++) {
                const int kvc = (nt << 3) + (fc << 1);
                sP[(kvc  )*PP + ra]     = f2tf(s[nt][0]);
                sP[(kvc+1)*PP + ra]     = f2tf(s[nt][1]);
                sP[(kvc  )*PP + ra + 8] = f2tf(s[nt][2]);
                sP[(kvc+1)*PP + ra + 8] = f2tf(s[nt][3]);
            }
        }
        __syncwarp();

        // O += P @ V  (V fragments: cvt at use)
#pragma unroll
        for (int ks = 0; ks < 8; ks++) {
            const int kb = ks << 3;
            const int m = w << 4;
            unsigned a0 = sP[(kb+fc  )*PP + m + fr];
            unsigned a1 = sP[(kb+fc  )*PP + m + fr + 8];
            unsigned a2 = sP[(kb+fc+4)*PP + m + fr];
            unsigned a3 = sP[(kb+fc+4)*PP + m + fr + 8];
#pragma unroll
            for (int nt = 0; nt < 8; nt++) {
                const int dn = (nt << 3) + fr;
                unsigned b0 = f2tf(Vt[(kb + fc    ) * VP_ + dn]);
                unsigned b1 = f2tf(Vt[(kb + fc + 4) * VP_ + dn]);
                mma_tf32(o[nt], a0, a1, a2, a3, b0, b1);
            }
        }
    }

    // epilogue
    const float invA = 1.0f / lA;
    const float invB = 1.0f / lB;
    float* Op = Oo + (size_t)b * SS * DD + h * HD;
    const int ra = q0 + (w << 4) + fr;
#pragma unroll
    for (int nt = 0; nt < 8; nt++) {
        const int col = (nt << 3) + (fc << 1);
        *(float2*)(Op + (size_t)ra * DD + col) =
            make_float2(o[nt][0] * invA, o[nt][1] * invA);
        *(float2*)(Op + (size_t)(ra + 8) * DD + col) =
            make_float2(o[nt][2] * invB, o[nt][3] * invB);
    }
}

// ---------------- launch ----------------------------------------------------
extern "C" void kernel_launch(void* const* d_in, const int* in_sizes, int n_in,
                              void* d_out, int out_size)
{
    (void)in_sizes; (void)n_in; (void)out_size;
    const float* tokens = (const float*)d_in[0];
    const float* qkv_w  = (const float*)d_in[1];
    const float* qkv_b  = (const float*)d_in[2];
    const float* out_w  = (const float*)d_in[3];
    const float* out_b  = (const float*)d_in[4];
    float* out = (float*)d_out;

    float *qkv_s, *ao_s;
    cudaGetSymbolAddress((void**)&qkv_s, g_qkv);
    cudaGetSymbolAddress((void**)&ao_s, g_ao);

    static int smem_set = 0;
    if (!smem_set) {
        cudaFuncSetAttribute(attn_tf32, cudaFuncAttributeMaxDynamicSharedMemorySize, ATTN_SMEM);
        smem_set = 1;
    }

    // 1) QKV projection (tf32)
    gemm_tf32_nt<<<dim3(N1 / 128, M1 / 128), 256>>>(tokens, qkv_w, qkv_b, qkv_s, M1, N1, KD);
    // 2) RoPE + normalize (+SCALE on q) + split
    rope_kernel<<<(BB * HH * SS) / 4, dim3(32, 4)>>>();
    // 3) flash attention (tf32, BM=128, cp.async pipeline)
    attn_tf32<<<dim3(SS / 128, NBH), 256, ATTN_SMEM>>>(ao_s);
    // 4) output projection (tf32)
    gemm_tf32_nt<<<dim3(DD / 128, M1 / 128), 256>>>(ao_s, out_w, out_b, out, M1, DD, KD);
}

// round 5
// speedup vs baseline: 3.4101x; 1.2035x over previous
#include <cuda_runtime.h>
#include <math.h>

#define BB 2
#define SS 2048
#define DD 1024
#define HH 16
#define HD 64
#define M1 (BB*SS)      // 4096
#define N1 (3*DD)       // 3072
#define KD DD           // 1024
#define NBH (BB*HH)     // 32
#define SCALE 0.125f

// ---------------- scratch (device globals; no allocations allowed) ----------
__device__ float g_qkv[(size_t)M1 * N1];
__device__ float g_q[(size_t)NBH * SS * HD];     // [bh][s][d], tf32-rounded, q pre-scaled
__device__ float g_k[(size_t)NBH * SS * HD];     // [bh][s][d], tf32-rounded
__device__ float g_v[(size_t)NBH * HD * SS];     // [bh][d][s], tf32-rounded (TRANSPOSED)
__device__ float g_ao[(size_t)BB * SS * DD];     // tf32-rounded
__device__ float g_tokr[(size_t)M1 * KD];        // tf32-rounded tokens
__device__ float g_wr[(size_t)N1 * KD];          // tf32-rounded qkv_w
__device__ float g_owr[(size_t)DD * DD];         // tf32-rounded out_w

// ---------------- helpers ----------------------------------------------------
__device__ __forceinline__ unsigned f2tf(float x) {
    unsigned u;
    asm("cvt.rna.tf32.f32 %0, %1;" : "=r"(u) : "f"(x));
    return u;
}
__device__ __forceinline__ float rtf(float x) { return __uint_as_float(f2tf(x)); }

__device__ __forceinline__ void mma_tf32(float* c,
    unsigned a0, unsigned a1, unsigned a2, unsigned a3,
    unsigned b0, unsigned b1)
{
    asm volatile(
        "mma.sync.aligned.m16n8k8.row.col.f32.tf32.tf32.f32 "
        "{%0,%1,%2,%3},{%4,%5,%6,%7},{%8,%9},{%0,%1,%2,%3};"
        : "+f"(c[0]), "+f"(c[1]), "+f"(c[2]), "+f"(c[3])
        : "r"(a0), "r"(a1), "r"(a2), "r"(a3), "r"(b0), "r"(b1));
}
__device__ __forceinline__ void cp16(unsigned s, const void* g) {
    asm volatile("cp.async.cg.shared.global [%0], [%1], 16;" :: "r"(s), "l"(g));
}
__device__ __forceinline__ void cp_commit() {
    asm volatile("cp.async.commit_group;");
}
template<int N> __device__ __forceinline__ void cp_wait() {
    asm volatile("cp.async.wait_group %0;" :: "n"(N));
}
#define LDSM4(r0, r1, r2, r3, addr) \
    asm volatile("ldmatrix.sync.aligned.m8n8.x4.shared.b16 {%0,%1,%2,%3}, [%4];" \
        : "=r"(r0), "=r"(r1), "=r"(r2), "=r"(r3) : "r"(addr))

// ---------------- tf32 rounding pass (grid-stride, float4) ------------------
__global__ void round_tf_kernel(const float4* __restrict__ src,
                                float4* __restrict__ dst, int n4)
{
    for (int i = blockIdx.x * blockDim.x + threadIdx.x; i < n4;
         i += gridDim.x * blockDim.x) {
        float4 v = src[i];
        v.x = rtf(v.x); v.y = rtf(v.y); v.z = rtf(v.z); v.w = rtf(v.w);
        dst[i] = v;
    }
}

// ---------------- tf32 GEMM via ldmatrix + 3-stage cp.async -----------------
// C[M,N] = A[M,K] @ W[N,K]^T + bias. A,W pre-rounded to tf32.
// smem tiles [128 rows][16 k + 4 pad] (pitch 20 -> conflict-free LDSM).
#define GPW 20
#define GSTG (128 * GPW)                 // words per tensor per stage
#define GEMM_SMEM (3 * 2 * GSTG * 4)     // 61440 bytes

__global__ __launch_bounds__(256) void gemm_tf32_ldsm(
    const float* __restrict__ A, const float* __restrict__ W,
    const float* __restrict__ bias, float* __restrict__ C,
    int M, int N, int K)
{
    extern __shared__ __align__(16) unsigned gsm[];
    const unsigned sA_u = (unsigned)__cvta_generic_to_shared(gsm);
    const unsigned sB_u = sA_u + 3 * GSTG * 4;

    const int tid = threadIdx.x;
    const int bm = blockIdx.y << 7;
    const int bn = blockIdx.x << 7;
    const int w = tid >> 5;
    const int lane = tid & 31;
    const int wm = (w & 1) << 6;
    const int wn = (w >> 1) << 5;
    const int fr = lane >> 2;
    const int fc = lane & 3;

    // cp.async coords: row 0..127, col base 0 or 8 words
    const int lrow = tid >> 1;
    const int lcb = (tid & 1) << 3;
    const float* Asrc = A + (size_t)(bm + lrow) * K + lcb;
    const float* Wsrc = W + (size_t)(bn + lrow) * K + lcb;
    const unsigned dA0 = sA_u + (lrow * GPW + lcb) * 4;
    const unsigned dB0 = sB_u + (lrow * GPW + lcb) * 4;

    // LDSM byte offsets (within a stage)
    const unsigned a_off = ((wm + (lane & 15)) * GPW + ((lane >> 4) << 2)) * 4;
    const unsigned b_off = ((wn + (lane & 7) + ((lane >> 4) << 3)) * GPW
                            + ((lane & 8) ? 4 : 0)) * 4;

    float acc[4][4][4];
#pragma unroll
    for (int mt = 0; mt < 4; mt++)
#pragma unroll
        for (int nt = 0; nt < 4; nt++)
#pragma unroll
            for (int i = 0; i < 4; i++) acc[mt][nt][i] = 0.f;

    const int nk = K >> 4;
    auto issue = [&](int kt) {
        const unsigned so = (kt % 3) * GSTG * 4;
        const float* a = Asrc + ((size_t)kt << 4);
        const float* b = Wsrc + ((size_t)kt << 4);
        cp16(dA0 + so, a);      cp16(dA0 + so + 16, a + 4);
        cp16(dB0 + so, b);      cp16(dB0 + so + 16, b + 4);
        cp_commit();
    };

    issue(0); issue(1);

    for (int kt = 0; kt < nk; kt++) {
        if (kt + 1 < nk) cp_wait<1>(); else cp_wait<0>();
        __syncthreads();
        if (kt + 2 < nk) issue(kt + 2);

        const unsigned sa = sA_u + (kt % 3) * GSTG * 4;
        const unsigned sb = sB_u + (kt % 3) * GSTG * 4;
#pragma unroll
        for (int ks = 0; ks < 2; ks++) {
            const unsigned kbb = ks * 32;   // 8 words
            unsigned af[4][4], bf[4][2];
#pragma unroll
            for (int mt = 0; mt < 4; mt++)
                LDSM4(af[mt][0], af[mt][1], af[mt][2], af[mt][3],
                      sa + a_off + mt * (16 * GPW * 4) + kbb);
#pragma unroll
            for (int p = 0; p < 2; p++)
                LDSM4(bf[2*p][0], bf[2*p][1], bf[2*p+1][0], bf[2*p+1][1],
                      sb + b_off + p * (16 * GPW * 4) + kbb);
#pragma unroll
            for (int mt = 0; mt < 4; mt++)
#pragma unroll
                for (int nt = 0; nt < 4; nt++)
                    mma_tf32(acc[mt][nt], af[mt][0], af[mt][1], af[mt][2], af[mt][3],
                             bf[nt][0], bf[nt][1]);
        }
    }

#pragma unroll
    for (int mt = 0; mt < 4; mt++) {
        const int row = bm + wm + (mt << 4) + fr;
#pragma unroll
        for (int nt = 0; nt < 4; nt++) {
            const int col = bn + wn + (nt << 3) + (fc << 1);
            *(float2*)(C + (size_t)row * N + col) =
                make_float2(acc[mt][nt][0] + bias[col], acc[mt][nt][1] + bias[col + 1]);
            *(float2*)(C + (size_t)(row + 8) * N + col) =
                make_float2(acc[mt][nt][2] + bias[col], acc[mt][nt][3] + bias[col + 1]);
        }
    }
}

// ---------------- RoPE + L2-normalize + tf32 round + V transpose ------------
// block = 64 consecutive tokens of one bh; 4 warps x 16 tokens each.
__global__ __launch_bounds__(128) void rope_kernel()
{
    __shared__ float sVt[64][65];
    const int tid = threadIdx.x;
    const int w = tid >> 5;
    const int f = tid & 31;
    const int blk = blockIdx.x;
    const int bh = blk >> 5;              // 32 blocks per bh
    const int s0 = (blk & 31) << 6;
    const int b = bh >> 4, h = bh & 15;

    const double invd = exp(-(double)f * (9.210340371976184 / 32.0));

#pragma unroll 1
    for (int t = 0; t < 16; t++) {
        const int sl = (w << 4) + t;
        const int s = s0 + sl;
        float sn, cs;
        sincosf((float)((double)s * invd), &sn, &cs);

        const float* src = g_qkv + (size_t)(b * SS + s) * N1 + h * HD;
        float2 qv = *(const float2*)(src + 2 * f);
        float2 kv = *(const float2*)(src + DD + 2 * f);
        float2 vv = *(const float2*)(src + 2 * DD + 2 * f);

        const size_t dst = ((size_t)bh * SS + s) * HD + 2 * f;
        // Q (scaled by SCALE) -> rounded
        {
            float re = qv.x * cs - qv.y * sn;
            float ro = qv.x * sn + qv.y * cs;
            float sq = re * re + ro * ro;
#pragma unroll
            for (int msk = 16; msk > 0; msk >>= 1) sq += __shfl_xor_sync(0xffffffffu, sq, msk);
            float inv = SCALE / fmaxf(sqrtf(sq), 1e-12f);
            *(float2*)(g_q + dst) = make_float2(rtf(re * inv), rtf(ro * inv));
        }
        // K -> rounded
        {
            float re = kv.x * cs - kv.y * sn;
            float ro = kv.x * sn + kv.y * cs;
            float sq = re * re + ro * ro;
#pragma unroll
            for (int msk = 16; msk > 0; msk >>= 1) sq += __shfl_xor_sync(0xffffffffu, sq, msk);
            float inv = 1.0f / fmaxf(sqrtf(sq), 1e-12f);
            *(float2*)(g_k + dst) = make_float2(rtf(re * inv), rtf(ro * inv));
        }
        // V staged for transpose (rounded)
        sVt[sl][2 * f]     = rtf(vv.x);
        sVt[sl][2 * f + 1] = rtf(vv.y);
    }
    __syncthreads();

    // write V transposed: g_v[bh][d][s]
#pragma unroll 1
    for (int t = 0; t < 16; t++) {
        const int d = (w << 4) + t;
        float* dst = g_v + ((size_t)bh * HD + d) * SS + s0;
        dst[f]      = sVt[f][d];
        dst[f + 32] = sVt[f + 32][d];
    }
}

// ---------------- tf32 flash attention: ldmatrix + cp.async -----------------
// sK [kv][d] pitch 68, sV [d][kv] pitch 68 (3 stages each), sP [m][kv] pitch 68.
#define ATP 68
#define KVW (64 * ATP)                       // 4352 words
#define ATTN_SMEM ((3 * KVW * 2 + 128 * ATP) * 4)   // 139264 bytes

__global__ __launch_bounds__(256) void attn_tf32_ldsm(float* __restrict__ Oo)
{
    extern __shared__ __align__(16) unsigned smem_[];
    unsigned* sP = smem_ + 6 * KVW;
    const unsigned sK_u = (unsigned)__cvta_generic_to_shared(smem_);
    const unsigned sV_u = sK_u + 3 * KVW * 4;
    const unsigned sP_u = sK_u + 6 * KVW * 4;

    const int tid = threadIdx.x;
    const int w = tid >> 5;
    const int lane = tid & 31;
    const int fr = lane >> 2;
    const int fc = lane & 3;
    const int bh = blockIdx.y;
    const int b = bh >> 4, h = bh & 15;
    const int q0 = blockIdx.x << 7;

    const float* Qp = g_q + (size_t)bh * SS * HD;
    const float* Kp = g_k + (size_t)bh * SS * HD;
    const float* Vp = g_v + (size_t)bh * HD * SS;

    // loaders
    const int krow = tid >> 2;               // 0..63
    const int kcb = (tid & 3) << 2;          // word col base 0,4,8,12 (+16t)
    const int qrow = tid >> 1;               // 0..127
    const int qcb = (tid & 1) << 2;          // 0 or 4 (+8t)

    auto issueKV = [&](int jt) {
        const unsigned so = (jt % 3) * KVW * 4;
        const float* gK = Kp + ((size_t)(jt * 64 + krow)) * HD;
        const float* gV = Vp + (size_t)krow * SS + jt * 64;
#pragma unroll
        for (int t = 0; t < 4; t++) {
            const int c = kcb + (t << 4);
            cp16(sK_u + so + (krow * ATP + c) * 4, gK + c);
            cp16(sV_u + so + (krow * ATP + c) * 4, gV + c);
        }
        cp_commit();
    };

    // stage Q
    {
        const float* gQ = Qp + (size_t)(q0 + qrow) * HD;
#pragma unroll
        for (int t = 0; t < 8; t++) {
            const int c = qcb + (t << 3);
            cp16(sP_u + (qrow * ATP + c) * 4, gQ + c);
        }
        cp_commit();
    }
    issueKV(0); issueKV(1);

    cp_wait<2>();
    __syncthreads();

    // extract Q fragments via ldmatrix (held for the whole kernel)
    const unsigned a_off = (((w << 4) + (lane & 15)) * ATP + ((lane >> 4) << 2)) * 4;
    unsigned qf[8][4];
#pragma unroll
    for (int ks = 0; ks < 8; ks++)
        LDSM4(qf[ks][0], qf[ks][1], qf[ks][2], qf[ks][3], sP_u + a_off + ks * 32);

    const unsigned b_off = (((lane & 7) + ((lane >> 4) << 3)) * ATP
                            + ((lane & 8) ? 4 : 0)) * 4;

    float o[8][4];
#pragma unroll
    for (int nt = 0; nt < 8; nt++)
#pragma unroll
        for (int i = 0; i < 4; i++) o[nt][i] = 0.f;
    float mA = -1e30f, mB = -1e30f, lA = 0.f, lB = 0.f;

    const int NT = SS / 64;   // 32
    for (int jt = 0; jt < NT; jt++) {
        if (jt + 1 < NT) cp_wait<1>(); else cp_wait<0>();
        __syncthreads();
        if (jt + 2 < NT) issueKV(jt + 2);

        const unsigned Ktu = sK_u + (jt % 3) * KVW * 4;
        const unsigned Vtu = sV_u + (jt % 3) * KVW * 4;

        // S = Q K^T
        float s[8][4];
#pragma unroll
        for (int nt = 0; nt < 8; nt++)
#pragma unroll
            for (int i = 0; i < 4; i++) s[nt][i] = 0.f;
#pragma unroll
        for (int ks = 0; ks < 8; ks++) {
            const unsigned kbb = ks * 32;
            unsigned bf[8][2];
#pragma unroll
            for (int p = 0; p < 4; p++)
                LDSM4(bf[2*p][0], bf[2*p][1], bf[2*p+1][0], bf[2*p+1][1],
                      Ktu + b_off + p * (16 * ATP * 4) + kbb);
#pragma unroll
            for (int nt = 0; nt < 8; nt++)
                mma_tf32(s[nt], qf[ks][0], qf[ks][1], qf[ks][2], qf[ks][3],
                         bf[nt][0], bf[nt][1]);
        }

        // online softmax (rows fr -> A, fr+8 -> B)
        float mxA = -1e30f, mxB = -1e30f;
#pragma unroll
        for (int nt = 0; nt < 8; nt++) {
            mxA = fmaxf(mxA, fmaxf(s[nt][0], s[nt][1]));
            mxB = fmaxf(mxB, fmaxf(s[nt][2], s[nt][3]));
        }
        mxA = fmaxf(mxA, __shfl_xor_sync(0xffffffffu, mxA, 1));
        mxA = fmaxf(mxA, __shfl_xor_sync(0xffffffffu, mxA, 2));
        mxB = fmaxf(mxB, __shfl_xor_sync(0xffffffffu, mxB, 1));
        mxB = fmaxf(mxB, __shfl_xor_sync(0xffffffffu, mxB, 2));
        const float nmA = fmaxf(mA, mxA);
        const float nmB = fmaxf(mB, mxB);
        const float sclA = __expf(mA - nmA);
        const float sclB = __expf(mB - nmB);
        float sumA = 0.f, sumB = 0.f;
#pragma unroll
        for (int nt = 0; nt < 8; nt++) {
            s[nt][0] = __expf(s[nt][0] - nmA);
            s[nt][1] = __expf(s[nt][1] - nmA);
            s[nt][2] = __expf(s[nt][2] - nmB);
            s[nt][3] = __expf(s[nt][3] - nmB);
            sumA += s[nt][0] + s[nt][1];
            sumB += s[nt][2] + s[nt][3];
        }
        sumA += __shfl_xor_sync(0xffffffffu, sumA, 1);
        sumA += __shfl_xor_sync(0xffffffffu, sumA, 2);
        sumB += __shfl_xor_sync(0xffffffffu, sumB, 1);
        sumB += __shfl_xor_sync(0xffffffffu, sumB, 2);
        lA = lA * sclA + sumA;  mA = nmA;
        lB = lB * sclB + sumB;  mB = nmB;
#pragma unroll
        for (int nt = 0; nt < 8; nt++) {
            o[nt][0] *= sclA; o[nt][1] *= sclA;
            o[nt][2] *= sclB; o[nt][3] *= sclB;
        }

        // write P -> sP[m][kv] (warp-private rows), tf32-rounded
        {
            const int ra = (w << 4) + fr;
#pragma unroll
            for (int nt = 0; nt < 8; nt++) {
                const int cw = (nt << 3) + (fc << 1);
                *(uint2*)&sP[ra * ATP + cw] =
                    make_uint2(f2tf(s[nt][0]), f2tf(s[nt][1]));
                *(uint2*)&sP[(ra + 8) * ATP + cw] =
                    make_uint2(f2tf(s[nt][2]), f2tf(s[nt][3]));
            }
        }
        __syncwarp();

        // O += P @ V
#pragma unroll
        for (int ks = 0; ks < 8; ks++) {
            const unsigned kbb = ks * 32;
            unsigned af[4], vf[8][2];
            LDSM4(af[0], af[1], af[2], af[3], sP_u + a_off + kbb);
#pragma unroll
            for (int p = 0; p < 4; p++)
                LDSM4(vf[2*p][0], vf[2*p][1], vf[2*p+1][0], vf[2*p+1][1],
                      Vtu + b_off + p * (16 * ATP * 4) + kbb);
#pragma unroll
            for (int nt = 0; nt < 8; nt++)
                mma_tf32(o[nt], af[0], af[1], af[2], af[3], vf[nt][0], vf[nt][1]);
        }
    }

    // epilogue: normalize, tf32-round (feeds out-proj ldmatrix GEMM)
    const float invA = 1.0f / lA;
    const float invB = 1.0f / lB;
    float* Op = Oo + (size_t)b * SS * DD + h * HD;
    const int ra = q0 + (w << 4) + fr;
#pragma unroll
    for (int nt = 0; nt < 8; nt++) {
        const int col = (nt << 3) + (fc << 1);
        *(float2*)(Op + (size_t)ra * DD + col) =
            make_float2(rtf(o[nt][0] * invA), rtf(o[nt][1] * invA));
        *(float2*)(Op + (size_t)(ra + 8) * DD + col) =
            make_float2(rtf(o[nt][2] * invB), rtf(o[nt][3] * invB));
    }
}

// ---------------- launch ----------------------------------------------------
extern "C" void kernel_launch(void* const* d_in, const int* in_sizes, int n_in,
                              void* d_out, int out_size)
{
    (void)in_sizes; (void)n_in; (void)out_size;
    const float* tokens = (const float*)d_in[0];
    const float* qkv_w  = (const float*)d_in[1];
    const float* qkv_b  = (const float*)d_in[2];
    const float* out_w  = (const float*)d_in[3];
    const float* out_b  = (const float*)d_in[4];
    float* out = (float*)d_out;

    float *qkv_s, *ao_s, *tokr, *wr, *owr;
    cudaGetSymbolAddress((void**)&qkv_s, g_qkv);
    cudaGetSymbolAddress((void**)&ao_s, g_ao);
    cudaGetSymbolAddress((void**)&tokr, g_tokr);
    cudaGetSymbolAddress((void**)&wr, g_wr);
    cudaGetSymbolAddress((void**)&owr, g_owr);

    static int smem_set = 0;
    if (!smem_set) {
        cudaFuncSetAttribute(gemm_tf32_ldsm, cudaFuncAttributeMaxDynamicSharedMemorySize, GEMM_SMEM);
        cudaFuncSetAttribute(attn_tf32_ldsm, cudaFuncAttributeMaxDynamicSharedMemorySize, ATTN_SMEM);
        smem_set = 1;
    }

    // 0) pre-round inputs to tf32 (rna) so ldmatrix-fed MMAs see rna data
    round_tf_kernel<<<2048, 256>>>((const float4*)tokens, (float4*)tokr, M1 * KD / 4);
    round_tf_kernel<<<2048, 256>>>((const float4*)qkv_w, (float4*)wr, N1 * KD / 4);
    round_tf_kernel<<<1024, 256>>>((const float4*)out_w, (float4*)owr, DD * DD / 4);

    // 1) QKV projection (tf32 tensor cores, ldmatrix + cp.async)
    gemm_tf32_ldsm<<<dim3(N1 / 128, M1 / 128), 256, GEMM_SMEM>>>(tokr, wr, qkv_b, qkv_s, M1, N1, KD);
    // 2) RoPE + normalize (+SCALE on q) + round + V transpose
    rope_kernel<<<NBH * (SS / 64), 128>>>();
    // 3) flash attention (tf32, ldmatrix + cp.async)
    attn_tf32_ldsm<<<dim3(SS / 128, NBH), 256, ATTN_SMEM>>>(ao_s);
    // 4) output projection
    gemm_tf32_ldsm<<<dim3(DD / 128, M1 / 128), 256, GEMM_SMEM>>>(ao_s, owr, out_b, out, M1, DD, KD);
}

// round 6
// speedup vs baseline: 3.6804x; 1.0793x over previous
#include <cuda_runtime.h>
#include <math.h>

#define BB 2
#define SS 2048
#define DD 1024
#define HH 16
#define HD 64
#define M1 (BB*SS)      // 4096
#define N1 (3*DD)       // 3072
#define KD DD           // 1024
#define NBH (BB*HH)     // 32
#define SCALE 0.125f
#define LOG2E 1.44269504088896340736f

// ---------------- scratch (device globals; no allocations allowed) ----------
__device__ float g_qkv[(size_t)M1 * N1];
__device__ float g_q[(size_t)NBH * SS * HD];     // [bh][s][d], tf32, pre-scaled by SCALE*log2e
__device__ float g_k[(size_t)NBH * SS * HD];     // [bh][s][d], tf32
__device__ float g_v[(size_t)NBH * HD * SS];     // [bh][d][s], tf32 (transposed)
__device__ float g_ao[(size_t)BB * SS * DD];     // tf32
__device__ float g_tokr[(size_t)M1 * KD];
__device__ float g_wr[(size_t)N1 * KD];
__device__ float g_owr[(size_t)DD * DD];

// ---------------- helpers ----------------------------------------------------
__device__ __forceinline__ unsigned f2tf(float x) {
    unsigned u;
    asm("cvt.rna.tf32.f32 %0, %1;" : "=r"(u) : "f"(x));
    return u;
}
__device__ __forceinline__ float rtf(float x) { return __uint_as_float(f2tf(x)); }
__device__ __forceinline__ float ex2(float x) {
    float y;
    asm("ex2.approx.ftz.f32 %0, %1;" : "=f"(y) : "f"(x));
    return y;
}
__device__ __forceinline__ void mma_tf32(float* c,
    unsigned a0, unsigned a1, unsigned a2, unsigned a3,
    unsigned b0, unsigned b1)
{
    asm volatile(
        "mma.sync.aligned.m16n8k8.row.col.f32.tf32.tf32.f32 "
        "{%0,%1,%2,%3},{%4,%5,%6,%7},{%8,%9},{%0,%1,%2,%3};"
        : "+f"(c[0]), "+f"(c[1]), "+f"(c[2]), "+f"(c[3])
        : "r"(a0), "r"(a1), "r"(a2), "r"(a3), "r"(b0), "r"(b1));
}
__device__ __forceinline__ void cp16(unsigned s, const void* g) {
    asm volatile("cp.async.cg.shared.global [%0], [%1], 16;" :: "r"(s), "l"(g));
}
__device__ __forceinline__ void cp_commit() {
    asm volatile("cp.async.commit_group;");
}
template<int N> __device__ __forceinline__ void cp_wait() {
    asm volatile("cp.async.wait_group %0;" :: "n"(N));
}
#define LDSM4(r0, r1, r2, r3, addr) \
    asm volatile("ldmatrix.sync.aligned.m8n8.x4.shared.b16 {%0,%1,%2,%3}, [%4];" \
        : "=r"(r0), "=r"(r1), "=r"(r2), "=r"(r3) : "r"(addr))

// ---------------- tf32 rounding pass: 3 tensors in one launch ---------------
__global__ void round3_kernel(const float4* s0, float4* d0, int n0,
                              const float4* s1, float4* d1, int n1,
                              const float4* s2, float4* d2, int n2)
{
    const int total = n0 + n1 + n2;
    for (int i = blockIdx.x * blockDim.x + threadIdx.x; i < total;
         i += gridDim.x * blockDim.x) {
        const float4* s; float4* d; int j = i;
        if (j < n0) { s = s0; d = d0; }
        else if ((j -= n0) < n1) { s = s1; d = d1; }
        else { j -= n1; s = s2; d = d2; }
        float4 v = s[j];
        v.x = rtf(v.x); v.y = rtf(v.y); v.z = rtf(v.z); v.w = rtf(v.w);
        d[j] = v;
    }
}

// ---------------- tf32 GEMM: BK=32, 3-stage cp.async, ldmatrix --------------
// C[M,N] = A[M,K] @ W[N,K]^T + bias. A,W pre-rounded tf32.
// smem stage: [128 rows][32 k + 4 pad] (pitch 36, conflict-free LDSM).
#define GPW 36
#define GSTG (128 * GPW)                  // 4608 words / tensor / stage
#define GEMM_SMEM (3 * 2 * GSTG * 4)      // 110592 bytes

__global__ __launch_bounds__(256, 2) void gemm_tf32_ldsm(
    const float* __restrict__ A, const float* __restrict__ W,
    const float* __restrict__ bias, float* __restrict__ C,
    int M, int N, int K)
{
    extern __shared__ __align__(16) unsigned gsm[];
    const unsigned sA_u = (unsigned)__cvta_generic_to_shared(gsm);
    const unsigned sB_u = sA_u + 3 * GSTG * 4;

    const int tid = threadIdx.x;
    const int bm = blockIdx.y << 7;
    const int bn = blockIdx.x << 7;
    const int w = tid >> 5;
    const int lane = tid & 31;
    const int wm = (w & 1) << 6;
    const int wn = (w >> 1) << 5;
    const int fr = lane >> 2;
    const int fc = lane & 3;

    // cp.async coords: row 0..127, col half 0/16 words, 4 chunks of 16B
    const int lrow = tid >> 1;
    const int cb = (tid & 1) << 4;
    const float* Asrc = A + (size_t)(bm + lrow) * K + cb;
    const float* Wsrc = W + (size_t)(bn + lrow) * K + cb;
    const unsigned dA0 = sA_u + (lrow * GPW + cb) * 4;
    const unsigned dB0 = sB_u + (lrow * GPW + cb) * 4;

    // LDSM byte offsets (within stage)
    const unsigned a_off = ((wm + (lane & 15)) * GPW + ((lane >> 4) << 2)) * 4;
    const unsigned b_off = ((wn + (lane & 7) + ((lane >> 4) << 3)) * GPW
                            + ((lane & 8) ? 4 : 0)) * 4;

    float acc[4][4][4];
#pragma unroll
    for (int mt = 0; mt < 4; mt++)
#pragma unroll
        for (int nt = 0; nt < 4; nt++)
#pragma unroll
            for (int i = 0; i < 4; i++) acc[mt][nt][i] = 0.f;

    const int nk = K >> 5;   // BK=32
    auto issue = [&](int kt) {
        const unsigned so = (kt % 3) * GSTG * 4;
        const float* a = Asrc + ((size_t)kt << 5);
        const float* b = Wsrc + ((size_t)kt << 5);
#pragma unroll
        for (int t = 0; t < 4; t++) {
            cp16(dA0 + so + t * 16, a + t * 4);
            cp16(dB0 + so + t * 16, b + t * 4);
        }
        cp_commit();
    };

    issue(0); issue(1);

    for (int kt = 0; kt < nk; kt++) {
        if (kt + 1 < nk) cp_wait<1>(); else cp_wait<0>();
        __syncthreads();
        if (kt + 2 < nk) issue(kt + 2);

        const unsigned sa = sA_u + (kt % 3) * GSTG * 4;
        const unsigned sb = sB_u + (kt % 3) * GSTG * 4;
#pragma unroll
        for (int ks = 0; ks < 4; ks++) {
            const unsigned kbb = ks * 32;   // 8 words per k-step
            unsigned af[4][4], bf[4][2];
#pragma unroll
            for (int mt = 0; mt < 4; mt++)
                LDSM4(af[mt][0], af[mt][1], af[mt][2], af[mt][3],
                      sa + a_off + mt * (16 * GPW * 4) + kbb);
#pragma unroll
            for (int p = 0; p < 2; p++)
                LDSM4(bf[2*p][0], bf[2*p][1], bf[2*p+1][0], bf[2*p+1][1],
                      sb + b_off + p * (16 * GPW * 4) + kbb);
#pragma unroll
            for (int mt = 0; mt < 4; mt++)
#pragma unroll
                for (int nt = 0; nt < 4; nt++)
                    mma_tf32(acc[mt][nt], af[mt][0], af[mt][1], af[mt][2], af[mt][3],
                             bf[nt][0], bf[nt][1]);
        }
    }

#pragma unroll
    for (int mt = 0; mt < 4; mt++) {
        const int row = bm + wm + (mt << 4) + fr;
#pragma unroll
        for (int nt = 0; nt < 4; nt++) {
            const int col = bn + wn + (nt << 3) + (fc << 1);
            *(float2*)(C + (size_t)row * N + col) =
                make_float2(acc[mt][nt][0] + bias[col], acc[mt][nt][1] + bias[col + 1]);
            *(float2*)(C + (size_t)(row + 8) * N + col) =
                make_float2(acc[mt][nt][2] + bias[col], acc[mt][nt][3] + bias[col + 1]);
        }
    }
}

// ---------------- RoPE + L2-normalize + tf32 round + V transpose ------------
// q pre-scaled by SCALE*log2e (exp2-domain softmax downstream).
__global__ __launch_bounds__(128) void rope_kernel()
{
    __shared__ float sVt[64][65];
    const int tid = threadIdx.x;
    const int w = tid >> 5;
    const int f = tid & 31;
    const int blk = blockIdx.x;
    const int bh = blk >> 5;
    const int s0 = (blk & 31) << 6;
    const int b = bh >> 4, h = bh & 15;

    const double invd = exp(-(double)f * (9.210340371976184 / 32.0));

#pragma unroll 1
    for (int t = 0; t < 16; t++) {
        const int sl = (w << 4) + t;
        const int s = s0 + sl;
        float sn, cs;
        sincosf((float)((double)s * invd), &sn, &cs);

        const float* src = g_qkv + (size_t)(b * SS + s) * N1 + h * HD;
        float2 qv = *(const float2*)(src + 2 * f);
        float2 kv = *(const float2*)(src + DD + 2 * f);
        float2 vv = *(const float2*)(src + 2 * DD + 2 * f);

        const size_t dst = ((size_t)bh * SS + s) * HD + 2 * f;
        {
            float re = qv.x * cs - qv.y * sn;
            float ro = qv.x * sn + qv.y * cs;
            float sq = re * re + ro * ro;
#pragma unroll
            for (int msk = 16; msk > 0; msk >>= 1) sq += __shfl_xor_sync(0xffffffffu, sq, msk);
            float inv = (SCALE * LOG2E) / fmaxf(sqrtf(sq), 1e-12f);
            *(float2*)(g_q + dst) = make_float2(rtf(re * inv), rtf(ro * inv));
        }
        {
            float re = kv.x * cs - kv.y * sn;
            float ro = kv.x * sn + kv.y * cs;
            float sq = re * re + ro * ro;
#pragma unroll
            for (int msk = 16; msk > 0; msk >>= 1) sq += __shfl_xor_sync(0xffffffffu, sq, msk);
            float inv = 1.0f / fmaxf(sqrtf(sq), 1e-12f);
            *(float2*)(g_k + dst) = make_float2(rtf(re * inv), rtf(ro * inv));
        }
        sVt[sl][2 * f]     = rtf(vv.x);
        sVt[sl][2 * f + 1] = rtf(vv.y);
    }
    __syncthreads();

#pragma unroll 1
    for (int t = 0; t < 16; t++) {
        const int d = (w << 4) + t;
        float* dst = g_v + ((size_t)bh * HD + d) * SS + s0;
        dst[f]      = sVt[f][d];
        dst[f + 32] = sVt[f + 32][d];
    }
}

// ---------------- tf32 flash attention: 2-stage cp.async + ldmatrix ---------
// sK [kv][d] / sV [d][kv] pitch 68 x 2 stages; sP [m][kv] pitch 68.
#define ATP 68
#define KVW (64 * ATP)                       // 4352 words
#define ATTN_SMEM ((2 * KVW * 2 + 128 * ATP) * 4)   // 104448 bytes

__global__ __launch_bounds__(256, 2) void attn_tf32_ldsm(float* __restrict__ Oo)
{
    extern __shared__ __align__(16) unsigned smem_[];
    unsigned* sP = smem_ + 4 * KVW;
    const unsigned sK_u = (unsigned)__cvta_generic_to_shared(smem_);
    const unsigned sV_u = sK_u + 2 * KVW * 4;
    const unsigned sP_u = sK_u + 4 * KVW * 4;

    const int tid = threadIdx.x;
    const int w = tid >> 5;
    const int lane = tid & 31;
    const int fr = lane >> 2;
    const int fc = lane & 3;
    const int bh = blockIdx.y;
    const int b = bh >> 4, h = bh & 15;
    const int q0 = blockIdx.x << 7;

    const float* Qp = g_q + (size_t)bh * SS * HD;
    const float* Kp = g_k + (size_t)bh * SS * HD;
    const float* Vp = g_v + (size_t)bh * HD * SS;

    const int krow = tid >> 2;               // 0..63
    const int kcb = (tid & 3) << 2;
    const int qrow = tid >> 1;               // 0..127
    const int qcb = (tid & 1) << 2;

    auto issueKV = [&](int jt) {
        const unsigned so = (jt & 1) * KVW * 4;
        const float* gK = Kp + ((size_t)(jt * 64 + krow)) * HD;
        const float* gV = Vp + (size_t)krow * SS + jt * 64;
#pragma unroll
        for (int t = 0; t < 4; t++) {
            const int c = kcb + (t << 4);
            cp16(sK_u + so + (krow * ATP + c) * 4, gK + c);
            cp16(sV_u + so + (krow * ATP + c) * 4, gV + c);
        }
        cp_commit();
    };

    // stage Q
    {
        const float* gQ = Qp + (size_t)(q0 + qrow) * HD;
#pragma unroll
        for (int t = 0; t < 8; t++) {
            const int c = qcb + (t << 3);
            cp16(sP_u + (qrow * ATP + c) * 4, gQ + c);
        }
        cp_commit();
    }
    issueKV(0);

    cp_wait<1>();      // Q complete (KV0 may still be in flight)
    __syncthreads();

    // extract Q fragments (held in registers)
    const unsigned a_off = (((w << 4) + (lane & 15)) * ATP + ((lane >> 4) << 2)) * 4;
    unsigned qf[8][4];
#pragma unroll
    for (int ks = 0; ks < 8; ks++)
        LDSM4(qf[ks][0], qf[ks][1], qf[ks][2], qf[ks][3], sP_u + a_off + ks * 32);

    const unsigned b_off = (((lane & 7) + ((lane >> 4) << 3)) * ATP
                            + ((lane & 8) ? 4 : 0)) * 4;

    float o[8][4];
#pragma unroll
    for (int nt = 0; nt < 8; nt++)
#pragma unroll
        for (int i = 0; i < 4; i++) o[nt][i] = 0.f;
    float mA = -1e30f, mB = -1e30f, lA = 0.f, lB = 0.f;

    const int NT = SS / 64;   // 32
    for (int jt = 0; jt < NT; jt++) {
        cp_wait<0>();          // tile jt resident
        __syncthreads();       // all threads done reading buf (jt+1)&1 from jt-1
        if (jt + 1 < NT) issueKV(jt + 1);

        const unsigned Ktu = sK_u + (jt & 1) * KVW * 4;
        const unsigned Vtu = sV_u + (jt & 1) * KVW * 4;

        // S = Q K^T (exp2-domain scores: q carries SCALE*log2e)
        float s[8][4];
#pragma unroll
        for (int nt = 0; nt < 8; nt++)
#pragma unroll
            for (int i = 0; i < 4; i++) s[nt][i] = 0.f;
#pragma unroll
        for (int ks = 0; ks < 8; ks++) {
            const unsigned kbb = ks * 32;
            unsigned bf[8][2];
#pragma unroll
            for (int p = 0; p < 4; p++)
                LDSM4(bf[2*p][0], bf[2*p][1], bf[2*p+1][0], bf[2*p+1][1],
                      Ktu + b_off + p * (16 * ATP * 4) + kbb);
#pragma unroll
            for (int nt = 0; nt < 8; nt++)
                mma_tf32(s[nt], qf[ks][0], qf[ks][1], qf[ks][2], qf[ks][3],
                         bf[nt][0], bf[nt][1]);
        }

        // online softmax in exp2 domain
        float mxA = -1e30f, mxB = -1e30f;
#pragma unroll
        for (int nt = 0; nt < 8; nt++) {
            mxA = fmaxf(mxA, fmaxf(s[nt][0], s[nt][1]));
            mxB = fmaxf(mxB, fmaxf(s[nt][2], s[nt][3]));
        }
        mxA = fmaxf(mxA, __shfl_xor_sync(0xffffffffu, mxA, 1));
        mxA = fmaxf(mxA, __shfl_xor_sync(0xffffffffu, mxA, 2));
        mxB = fmaxf(mxB, __shfl_xor_sync(0xffffffffu, mxB, 1));
        mxB = fmaxf(mxB, __shfl_xor_sync(0xffffffffu, mxB, 2));
        const float nmA = fmaxf(mA, mxA);
        const float nmB = fmaxf(mB, mxB);
        const float sclA = ex2(mA - nmA);
        const float sclB = ex2(mB - nmB);
        float sumA = 0.f, sumB = 0.f;
#pragma unroll
        for (int nt = 0; nt < 8; nt++) {
            s[nt][0] = ex2(s[nt][0] - nmA);
            s[nt][1] = ex2(s[nt][1] - nmA);
            s[nt][2] = ex2(s[nt][2] - nmB);
            s[nt][3] = ex2(s[nt][3] - nmB);
            sumA += s[nt][0] + s[nt][1];
            sumB += s[nt][2] + s[nt][3];
        }
        sumA += __shfl_xor_sync(0xffffffffu, sumA, 1);
        sumA += __shfl_xor_sync(0xffffffffu, sumA, 2);
        sumB += __shfl_xor_sync(0xffffffffu, sumB, 1);
        sumB += __shfl_xor_sync(0xffffffffu, sumB, 2);
        lA = lA * sclA + sumA;  mA = nmA;
        lB = lB * sclB + sumB;  mB = nmB;
#pragma unroll
        for (int nt = 0; nt < 8; nt++) {
            o[nt][0] *= sclA; o[nt][1] *= sclA;
            o[nt][2] *= sclB; o[nt][3] *= sclB;
        }

        // write P -> sP[m][kv] (warp-private rows), tf32
        {
            const int ra = (w << 4) + fr;
#pragma unroll
            for (int nt = 0; nt < 8; nt++) {
                const int cw = (nt << 3) + (fc << 1);
                *(uint2*)&sP[ra * ATP + cw] =
                    make_uint2(f2tf(s[nt][0]), f2tf(s[nt][1]));
                *(uint2*)&sP[(ra + 8) * ATP + cw] =
                    make_uint2(f2tf(s[nt][2]), f2tf(s[nt][3]));
            }
        }
        __syncwarp();

        // O += P @ V
#pragma unroll
        for (int ks = 0; ks < 8; ks++) {
            const unsigned kbb = ks * 32;
            unsigned af[4], vf[8][2];
            LDSM4(af[0], af[1], af[2], af[3], sP_u + a_off + kbb);
#pragma unroll
            for (int p = 0; p < 4; p++)
                LDSM4(vf[2*p][0], vf[2*p][1], vf[2*p+1][0], vf[2*p+1][1],
                      Vtu + b_off + p * (16 * ATP * 4) + kbb);
#pragma unroll
            for (int nt = 0; nt < 8; nt++)
                mma_tf32(o[nt], af[0], af[1], af[2], af[3], vf[nt][0], vf[nt][1]);
        }
    }

    // epilogue: normalize + tf32 round (feeds out-proj)
    const float invA = 1.0f / lA;
    const float invB = 1.0f / lB;
    float* Op = Oo + (size_t)b * SS * DD + h * HD;
    const int ra = q0 + (w << 4) + fr;
#pragma unroll
    for (int nt = 0; nt < 8; nt++) {
        const int col = (nt << 3) + (fc << 1);
        *(float2*)(Op + (size_t)ra * DD + col) =
            make_float2(rtf(o[nt][0] * invA), rtf(o[nt][1] * invA));
        *(float2*)(Op + (size_t)(ra + 8) * DD + col) =
            make_float2(rtf(o[nt][2] * invB), rtf(o[nt][3] * invB));
    }
}

// ---------------- launch ----------------------------------------------------
extern "C" void kernel_launch(void* const* d_in, const int* in_sizes, int n_in,
                              void* d_out, int out_size)
{
    (void)in_sizes; (void)n_in; (void)out_size;
    const float* tokens = (const float*)d_in[0];
    const float* qkv_w  = (const float*)d_in[1];
    const float* qkv_b  = (const float*)d_in[2];
    const float* out_w  = (const float*)d_in[3];
    const float* out_b  = (const float*)d_in[4];
    float* out = (float*)d_out;

    float *qkv_s, *ao_s, *tokr, *wr, *owr;
    cudaGetSymbolAddress((void**)&qkv_s, g_qkv);
    cudaGetSymbolAddress((void**)&ao_s, g_ao);
    cudaGetSymbolAddress((void**)&tokr, g_tokr);
    cudaGetSymbolAddress((void**)&wr, g_wr);
    cudaGetSymbolAddress((void**)&owr, g_owr);

    static int smem_set = 0;
    if (!smem_set) {
        cudaFuncSetAttribute(gemm_tf32_ldsm, cudaFuncAttributeMaxDynamicSharedMemorySize, GEMM_SMEM);
        cudaFuncSetAttribute(attn_tf32_ldsm, cudaFuncAttributeMaxDynamicSharedMemorySize, ATTN_SMEM);
        smem_set = 1;
    }

    // 0) pre-round all GEMM operands to tf32 (rna) in one launch
    round3_kernel<<<2048, 256>>>(
        (const float4*)tokens, (float4*)tokr, M1 * KD / 4,
        (const float4*)qkv_w,  (float4*)wr,   N1 * KD / 4,
        (const float4*)out_w,  (float4*)owr,  DD * DD / 4);

    // 1) QKV projection
    gemm_tf32_ldsm<<<dim3(N1 / 128, M1 / 128), 256, GEMM_SMEM>>>(tokr, wr, qkv_b, qkv_s, M1, N1, KD);
    // 2) RoPE + normalize (+SCALE*log2e on q) + round + V transpose
    rope_kernel<<<NBH * (SS / 64), 128>>>();
    // 3) flash attention
    attn_tf32_ldsm<<<dim3(SS / 128, NBH), 256, ATTN_SMEM>>>(ao_s);
    // 4) output projection
    gemm_tf32_ldsm<<<dim3(DD / 128, M1 / 128), 256, GEMM_SMEM>>>(ao_s, owr, out_b, out, M1, DD, KD);
}

// round 7
// speedup vs baseline: 3.9727x; 1.0794x over previous
#include <cuda_runtime.h>
#include <cuda_bf16.h>
#include <math.h>

#define BB 2
#define SS 2048
#define DD 1024
#define HH 16
#define HD 64
#define M1 (BB*SS)      // 4096
#define N1 (3*DD)       // 3072
#define KD DD           // 1024
#define NBH (BB*HH)     // 32
#define SCALE 0.125f
#define LOG2E 1.44269504088896340736f

// ---------------- scratch (device globals; no allocations allowed) ----------
__device__ float g_qkv[(size_t)M1 * N1];
__device__ __nv_bfloat16 g_q[(size_t)NBH * SS * HD];  // [bh][s][d], bf16, pre-scaled SCALE*log2e
__device__ __nv_bfloat16 g_k[(size_t)NBH * SS * HD];  // [bh][s][d], bf16
__device__ float g_v[(size_t)NBH * HD * SS];          // [bh][d][s], tf32 (transposed)
__device__ float g_ao[(size_t)BB * SS * DD];          // tf32
__device__ float g_tokr[(size_t)M1 * KD];
__device__ float g_wr[(size_t)N1 * KD];
__device__ float g_owr[(size_t)DD * DD];

// ---------------- helpers ----------------------------------------------------
__device__ __forceinline__ unsigned f2tf(float x) {
    unsigned u;
    asm("cvt.rna.tf32.f32 %0, %1;" : "=r"(u) : "f"(x));
    return u;
}
__device__ __forceinline__ float rtf(float x) { return __uint_as_float(f2tf(x)); }
__device__ __forceinline__ float ex2(float x) {
    float y;
    asm("ex2.approx.ftz.f32 %0, %1;" : "=f"(y) : "f"(x));
    return y;
}
__device__ __forceinline__ void mma_tf32(float* c,
    unsigned a0, unsigned a1, unsigned a2, unsigned a3,
    unsigned b0, unsigned b1)
{
    asm volatile(
        "mma.sync.aligned.m16n8k8.row.col.f32.tf32.tf32.f32 "
        "{%0,%1,%2,%3},{%4,%5,%6,%7},{%8,%9},{%0,%1,%2,%3};"
        : "+f"(c[0]), "+f"(c[1]), "+f"(c[2]), "+f"(c[3])
        : "r"(a0), "r"(a1), "r"(a2), "r"(a3), "r"(b0), "r"(b1));
}
__device__ __forceinline__ void mma_bf16(float* c,
    unsigned a0, unsigned a1, unsigned a2, unsigned a3,
    unsigned b0, unsigned b1)
{
    asm volatile(
        "mma.sync.aligned.m16n8k16.row.col.f32.bf16.bf16.f32 "
        "{%0,%1,%2,%3},{%4,%5,%6,%7},{%8,%9},{%0,%1,%2,%3};"
        : "+f"(c[0]), "+f"(c[1]), "+f"(c[2]), "+f"(c[3])
        : "r"(a0), "r"(a1), "r"(a2), "r"(a3), "r"(b0), "r"(b1));
}
__device__ __forceinline__ void cp16(unsigned s, const void* g) {
    asm volatile("cp.async.cg.shared.global [%0], [%1], 16;" :: "r"(s), "l"(g));
}
__device__ __forceinline__ void cp_commit() {
    asm volatile("cp.async.commit_group;");
}
template<int N> __device__ __forceinline__ void cp_wait() {
    asm volatile("cp.async.wait_group %0;" :: "n"(N));
}
#define LDSM4(r0, r1, r2, r3, addr) \
    asm volatile("ldmatrix.sync.aligned.m8n8.x4.shared.b16 {%0,%1,%2,%3}, [%4];" \
        : "=r"(r0), "=r"(r1), "=r"(r2), "=r"(r3) : "r"(addr))

// ---------------- tf32 rounding pass: 3 tensors in one launch ---------------
__global__ void round3_kernel(const float4* s0, float4* d0, int n0,
                              const float4* s1, float4* d1, int n1,
                              const float4* s2, float4* d2, int n2)
{
    const int total = n0 + n1 + n2;
    for (int i = blockIdx.x * blockDim.x + threadIdx.x; i < total;
         i += gridDim.x * blockDim.x) {
        const float4* s; float4* d; int j = i;
        if (j < n0) { s = s0; d = d0; }
        else if ((j -= n0) < n1) { s = s1; d = d1; }
        else { j -= n1; s = s2; d = d2; }
        float4 v = s[j];
        v.x = rtf(v.x); v.y = rtf(v.y); v.z = rtf(v.z); v.w = rtf(v.w);
        d[j] = v;
    }
}

// ---------------- tf32 GEMM: BK=32, 3-stage cp.async, ldmatrix --------------
#define GPW 36
#define GSTG (128 * GPW)
#define GEMM_SMEM (3 * 2 * GSTG * 4)      // 110592 bytes

__global__ __launch_bounds__(256, 2) void gemm_tf32_ldsm(
    const float* __restrict__ A, const float* __restrict__ W,
    const float* __restrict__ bias, float* __restrict__ C,
    int M, int N, int K)
{
    extern __shared__ __align__(16) unsigned gsm[];
    const unsigned sA_u = (unsigned)__cvta_generic_to_shared(gsm);
    const unsigned sB_u = sA_u + 3 * GSTG * 4;

    const int tid = threadIdx.x;
    const int bm = blockIdx.y << 7;
    const int bn = blockIdx.x << 7;
    const int w = tid >> 5;
    const int lane = tid & 31;
    const int wm = (w & 1) << 6;
    const int wn = (w >> 1) << 5;
    const int fr = lane >> 2;
    const int fc = lane & 3;

    const int lrow = tid >> 1;
    const int cb = (tid & 1) << 4;
    const float* Asrc = A + (size_t)(bm + lrow) * K + cb;
    const float* Wsrc = W + (size_t)(bn + lrow) * K + cb;
    const unsigned dA0 = sA_u + (lrow * GPW + cb) * 4;
    const unsigned dB0 = sB_u + (lrow * GPW + cb) * 4;

    const unsigned a_off = ((wm + (lane & 15)) * GPW + ((lane >> 4) << 2)) * 4;
    const unsigned b_off = ((wn + (lane & 7) + ((lane >> 4) << 3)) * GPW
                            + ((lane & 8) ? 4 : 0)) * 4;

    float acc[4][4][4];
#pragma unroll
    for (int mt = 0; mt < 4; mt++)
#pragma unroll
        for (int nt = 0; nt < 4; nt++)
#pragma unroll
            for (int i = 0; i < 4; i++) acc[mt][nt][i] = 0.f;

    const int nk = K >> 5;
    auto issue = [&](int kt) {
        const unsigned so = (kt % 3) * GSTG * 4;
        const float* a = Asrc + ((size_t)kt << 5);
        const float* b = Wsrc + ((size_t)kt << 5);
#pragma unroll
        for (int t = 0; t < 4; t++) {
            cp16(dA0 + so + t * 16, a + t * 4);
            cp16(dB0 + so + t * 16, b + t * 4);
        }
        cp_commit();
    };

    issue(0); issue(1);

    for (int kt = 0; kt < nk; kt++) {
        if (kt + 1 < nk) cp_wait<1>(); else cp_wait<0>();
        __syncthreads();
        if (kt + 2 < nk) issue(kt + 2);

        const unsigned sa = sA_u + (kt % 3) * GSTG * 4;
        const unsigned sb = sB_u + (kt % 3) * GSTG * 4;
#pragma unroll
        for (int ks = 0; ks < 4; ks++) {
            const unsigned kbb = ks * 32;
            unsigned af[4][4], bf[4][2];
#pragma unroll
            for (int mt = 0; mt < 4; mt++)
                LDSM4(af[mt][0], af[mt][1], af[mt][2], af[mt][3],
                      sa + a_off + mt * (16 * GPW * 4) + kbb);
#pragma unroll
            for (int p = 0; p < 2; p++)
                LDSM4(bf[2*p][0], bf[2*p][1], bf[2*p+1][0], bf[2*p+1][1],
                      sb + b_off + p * (16 * GPW * 4) + kbb);
#pragma unroll
            for (int mt = 0; mt < 4; mt++)
#pragma unroll
                for (int nt = 0; nt < 4; nt++)
                    mma_tf32(acc[mt][nt], af[mt][0], af[mt][1], af[mt][2], af[mt][3],
                             bf[nt][0], bf[nt][1]);
        }
    }

#pragma unroll
    for (int mt = 0; mt < 4; mt++) {
        const int row = bm + wm + (mt << 4) + fr;
#pragma unroll
        for (int nt = 0; nt < 4; nt++) {
            const int col = bn + wn + (nt << 3) + (fc << 1);
            *(float2*)(C + (size_t)row * N + col) =
                make_float2(acc[mt][nt][0] + bias[col], acc[mt][nt][1] + bias[col + 1]);
            *(float2*)(C + (size_t)(row + 8) * N + col) =
                make_float2(acc[mt][nt][2] + bias[col], acc[mt][nt][3] + bias[col + 1]);
        }
    }
}

// ---------------- RoPE + L2-norm + (q,k -> bf16) + V tf32 transpose ---------
__global__ __launch_bounds__(128) void rope_kernel()
{
    __shared__ float sVt[64][65];
    const int tid = threadIdx.x;
    const int w = tid >> 5;
    const int f = tid & 31;
    const int blk = blockIdx.x;
    const int bh = blk >> 5;
    const int s0 = (blk & 31) << 6;
    const int b = bh >> 4, h = bh & 15;

    const double invd = exp(-(double)f * (9.210340371976184 / 32.0));

#pragma unroll 1
    for (int t = 0; t < 16; t++) {
        const int sl = (w << 4) + t;
        const int s = s0 + sl;
        float sn, cs;
        sincosf((float)((double)s * invd), &sn, &cs);

        const float* src = g_qkv + (size_t)(b * SS + s) * N1 + h * HD;
        float2 qv = *(const float2*)(src + 2 * f);
        float2 kv = *(const float2*)(src + DD + 2 * f);
        float2 vv = *(const float2*)(src + 2 * DD + 2 * f);

        const size_t dst = ((size_t)bh * SS + s) * HD + 2 * f;
        {
            float re = qv.x * cs - qv.y * sn;
            float ro = qv.x * sn + qv.y * cs;
            float sq = re * re + ro * ro;
#pragma unroll
            for (int msk = 16; msk > 0; msk >>= 1) sq += __shfl_xor_sync(0xffffffffu, sq, msk);
            float inv = (SCALE * LOG2E) / fmaxf(sqrtf(sq), 1e-12f);
            *(__nv_bfloat162*)(g_q + dst) = __floats2bfloat162_rn(re * inv, ro * inv);
        }
        {
            float re = kv.x * cs - kv.y * sn;
            float ro = kv.x * sn + kv.y * cs;
            float sq = re * re + ro * ro;
#pragma unroll
            for (int msk = 16; msk > 0; msk >>= 1) sq += __shfl_xor_sync(0xffffffffu, sq, msk);
            float inv = 1.0f / fmaxf(sqrtf(sq), 1e-12f);
            *(__nv_bfloat162*)(g_k + dst) = __floats2bfloat162_rn(re * inv, ro * inv);
        }
        sVt[sl][2 * f]     = rtf(vv.x);
        sVt[sl][2 * f + 1] = rtf(vv.y);
    }
    __syncthreads();

#pragma unroll 1
    for (int t = 0; t < 16; t++) {
        const int d = (w << 4) + t;
        float* dst = g_v + ((size_t)bh * HD + d) * SS + s0;
        dst[f]      = sVt[f][d];
        dst[f + 32] = sVt[f + 32][d];
    }
}

// ---------------- flash attention: bf16 QK^T + tf32 PV ----------------------
// sK: bf16 [kv][d] pitch 72 h, 2 stages. sV: tf32 [d][kv] pitch 68 w, 2 stages.
// sP: tf32 [m][kv] pitch 68 w (doubles as bf16 Q staging pitch 72 h).
#define KP2 72
#define VPW 68
#define PPW 68
#define KSTG (64 * KP2 * 2)                  // 9216 B
#define VSTG (64 * VPW * 4)                  // 17408 B
#define ATTN_SMEM (2 * KSTG + 2 * VSTG + 128 * PPW * 4)   // 88064 B

__global__ __launch_bounds__(256, 2) void attn_bf16_ldsm(float* __restrict__ Oo)
{
    extern __shared__ __align__(16) unsigned smem_[];
    unsigned* sP = smem_ + (2 * KSTG + 2 * VSTG) / 4;
    const unsigned sK_u = (unsigned)__cvta_generic_to_shared(smem_);
    const unsigned sV_u = sK_u + 2 * KSTG;
    const unsigned sP_u = sK_u + 2 * KSTG + 2 * VSTG;

    const int tid = threadIdx.x;
    const int w = tid >> 5;
    const int lane = tid & 31;
    const int fr = lane >> 2;
    const int fc = lane & 3;
    const int bh = blockIdx.y;
    const int b = bh >> 4, h = bh & 15;
    const int q0 = blockIdx.x << 7;

    const __nv_bfloat16* Qp = g_q + (size_t)bh * SS * HD;
    const __nv_bfloat16* Kp = g_k + (size_t)bh * SS * HD;
    const float* Vp = g_v + (size_t)bh * HD * SS;

    // cp.async coords
    const int krow = tid >> 2;               // 0..63
    const int kc = tid & 3;                  // 4 threads per row
    const int qrow = tid >> 1;               // 0..127
    const int qc = tid & 1;

    auto issueKV = [&](int jt) {
        const unsigned soK = (jt & 1) * KSTG;
        const unsigned soV = (jt & 1) * VSTG;
        const __nv_bfloat16* gK = Kp + (size_t)(jt * 64 + krow) * HD;
        const float* gV = Vp + (size_t)krow * SS + jt * 64;
        // K: 64 bf16 = 128 B per row -> 8 chunks, 2 per thread
#pragma unroll
        for (int t = 0; t < 2; t++) {
            const int c = kc + (t << 2);     // chunk 0..7 (8 bf16 each)
            cp16(sK_u + soK + (krow * KP2 + (c << 3)) * 2, gK + (c << 3));
        }
        // V: 64 fp32 = 256 B per row -> 16 chunks, 4 per thread
#pragma unroll
        for (int t = 0; t < 4; t++) {
            const int c = (kc << 2) + (t << 4);   // word col 0..60
            cp16(sV_u + soV + (krow * VPW + c) * 4, gV + c);
        }
        cp_commit();
    };

    // stage Q (bf16, pitch KP2) into sP region
    {
        const __nv_bfloat16* gQ = Qp + (size_t)(q0 + qrow) * HD;
#pragma unroll
        for (int t = 0; t < 4; t++) {
            const int c = (qc << 2) + t;     // chunk 0..7
            cp16(sP_u + (qrow * KP2 + (c << 3)) * 2, gQ + (c << 3));
        }
        cp_commit();
    }
    issueKV(0);

    cp_wait<1>();      // Q resident
    __syncthreads();

    // Q fragments (bf16 A-frags, m16n8k16), held in registers
    const unsigned a_q_off = (((w << 4) + (lane & 15)) * KP2 + ((lane >> 4) << 3)) * 2;
    unsigned qf[4][4];
#pragma unroll
    for (int ks = 0; ks < 4; ks++)
        LDSM4(qf[ks][0], qf[ks][1], qf[ks][2], qf[ks][3], sP_u + a_q_off + ks * 32);

    // K B-frag lane offset (non-trans: K[kv][d] is col-major B)
    const unsigned kb_off = (((lane & 7) + ((lane >> 4) << 3)) * KP2
                             + (((lane >> 3) & 1) << 3)) * 2;
    // V / P lane offsets (tf32 path, unchanged)
    const unsigned v_b_off = (((lane & 7) + ((lane >> 4) << 3)) * VPW
                              + ((lane & 8) ? 4 : 0)) * 4;
    const unsigned a_p_off = (((w << 4) + (lane & 15)) * PPW + ((lane >> 4) << 2)) * 4;

    float o[8][4];
#pragma unroll
    for (int nt = 0; nt < 8; nt++)
#pragma unroll
        for (int i = 0; i < 4; i++) o[nt][i] = 0.f;
    float mA = -1e30f, mB = -1e30f, lA = 0.f, lB = 0.f;

    const int NT = SS / 64;   // 32
    for (int jt = 0; jt < NT; jt++) {
        cp_wait<0>();
        __syncthreads();
        if (jt + 1 < NT) issueKV(jt + 1);

        const unsigned Ktu = sK_u + (jt & 1) * KSTG;
        const unsigned Vtu = sV_u + (jt & 1) * VSTG;

        // S = Q K^T (bf16, k16 steps)
        float s[8][4];
#pragma unroll
        for (int nt = 0; nt < 8; nt++)
#pragma unroll
            for (int i = 0; i < 4; i++) s[nt][i] = 0.f;
#pragma unroll
        for (int ks = 0; ks < 4; ks++) {
            unsigned bf[8][2];
#pragma unroll
            for (int ng = 0; ng < 4; ng++)
                LDSM4(bf[2*ng][0], bf[2*ng][1], bf[2*ng+1][0], bf[2*ng+1][1],
                      Ktu + kb_off + ng * (16 * KP2 * 2) + ks * 32);
#pragma unroll
            for (int nt = 0; nt < 8; nt++)
                mma_bf16(s[nt], qf[ks][0], qf[ks][1], qf[ks][2], qf[ks][3],
                         bf[nt][0], bf[nt][1]);
        }

        // online softmax (exp2 domain; q carries SCALE*log2e)
        float mxA = -1e30f, mxB = -1e30f;
#pragma unroll
        for (int nt = 0; nt < 8; nt++) {
            mxA = fmaxf(mxA, fmaxf(s[nt][0], s[nt][1]));
            mxB = fmaxf(mxB, fmaxf(s[nt][2], s[nt][3]));
        }
        mxA = fmaxf(mxA, __shfl_xor_sync(0xffffffffu, mxA, 1));
        mxA = fmaxf(mxA, __shfl_xor_sync(0xffffffffu, mxA, 2));
        mxB = fmaxf(mxB, __shfl_xor_sync(0xffffffffu, mxB, 1));
        mxB = fmaxf(mxB, __shfl_xor_sync(0xffffffffu, mxB, 2));
        const float nmA = fmaxf(mA, mxA);
        const float nmB = fmaxf(mB, mxB);
        const float sclA = ex2(mA - nmA);
        const float sclB = ex2(mB - nmB);
        float sumA = 0.f, sumB = 0.f;
#pragma unroll
        for (int nt = 0; nt < 8; nt++) {
            s[nt][0] = ex2(s[nt][0] - nmA);
            s[nt][1] = ex2(s[nt][1] - nmA);
            s[nt][2] = ex2(s[nt][2] - nmB);
            s[nt][3] = ex2(s[nt][3] - nmB);
            sumA += s[nt][0] + s[nt][1];
            sumB += s[nt][2] + s[nt][3];
        }
        sumA += __shfl_xor_sync(0xffffffffu, sumA, 1);
        sumA += __shfl_xor_sync(0xffffffffu, sumA, 2);
        sumB += __shfl_xor_sync(0xffffffffu, sumB, 1);
        sumB += __shfl_xor_sync(0xffffffffu, sumB, 2);
        lA = lA * sclA + sumA;  mA = nmA;
        lB = lB * sclB + sumB;  mB = nmB;
#pragma unroll
        for (int nt = 0; nt < 8; nt++) {
            o[nt][0] *= sclA; o[nt][1] *= sclA;
            o[nt][2] *= sclB; o[nt][3] *= sclB;
        }

        // write P -> sP[m][kv] (warp-private rows), tf32
        __syncwarp();
        {
            const int ra = (w << 4) + fr;
#pragma unroll
            for (int nt = 0; nt < 8; nt++) {
                const int cw = (nt << 3) + (fc << 1);
                *(uint2*)&sP[ra * PPW + cw] =
                    make_uint2(f2tf(s[nt][0]), f2tf(s[nt][1]));
                *(uint2*)&sP[(ra + 8) * PPW + cw] =
                    make_uint2(f2tf(s[nt][2]), f2tf(s[nt][3]));
            }
        }
        __syncwarp();

        // O += P @ V (tf32, k8 steps)
#pragma unroll
        for (int ks = 0; ks < 8; ks++) {
            const unsigned kbb = ks * 32;
            unsigned af[4], vf[8][2];
            LDSM4(af[0], af[1], af[2], af[3], sP_u + a_p_off + kbb);
#pragma unroll
            for (int p = 0; p < 4; p++)
                LDSM4(vf[2*p][0], vf[2*p][1], vf[2*p+1][0], vf[2*p+1][1],
                      Vtu + v_b_off + p * (16 * VPW * 4) + kbb);
#pragma unroll
            for (int nt = 0; nt < 8; nt++)
                mma_tf32(o[nt], af[0], af[1], af[2], af[3], vf[nt][0], vf[nt][1]);
        }
    }

    // epilogue: normalize + tf32 round (feeds out-proj)
    const float invA = 1.0f / lA;
    const float invB = 1.0f / lB;
    float* Op = Oo + (size_t)b * SS * DD + h * HD;
    const int ra = q0 + (w << 4) + fr;
#pragma unroll
    for (int nt = 0; nt < 8; nt++) {
        const int col = (nt << 3) + (fc << 1);
        *(float2*)(Op + (size_t)ra * DD + col) =
            make_float2(rtf(o[nt][0] * invA), rtf(o[nt][1] * invA));
        *(float2*)(Op + (size_t)(ra + 8) * DD + col) =
            make_float2(rtf(o[nt][2] * invB), rtf(o[nt][3] * invB));
    }
}

// ---------------- launch ----------------------------------------------------
extern "C" void kernel_launch(void* const* d_in, const int* in_sizes, int n_in,
                              void* d_out, int out_size)
{
    (void)in_sizes; (void)n_in; (void)out_size;
    const float* tokens = (const float*)d_in[0];
    const float* qkv_w  = (const float*)d_in[1];
    const float* qkv_b  = (const float*)d_in[2];
    const float* out_w  = (const float*)d_in[3];
    const float* out_b  = (const float*)d_in[4];
    float* out = (float*)d_out;

    float *qkv_s, *ao_s, *tokr, *wr, *owr;
    cudaGetSymbolAddress((void**)&qkv_s, g_qkv);
    cudaGetSymbolAddress((void**)&ao_s, g_ao);
    cudaGetSymbolAddress((void**)&tokr, g_tokr);
    cudaGetSymbolAddress((void**)&wr, g_wr);
    cudaGetSymbolAddress((void**)&owr, g_owr);

    static int smem_set = 0;
    if (!smem_set) {
        cudaFuncSetAttribute(gemm_tf32_ldsm, cudaFuncAttributeMaxDynamicSharedMemorySize, GEMM_SMEM);
        cudaFuncSetAttribute(attn_bf16_ldsm, cudaFuncAttributeMaxDynamicSharedMemorySize, ATTN_SMEM);
        smem_set = 1;
    }

    // 0) pre-round all GEMM operands to tf32 (rna) in one launch
    round3_kernel<<<2048, 256>>>(
        (const float4*)tokens, (float4*)tokr, M1 * KD / 4,
        (const float4*)qkv_w,  (float4*)wr,   N1 * KD / 4,
        (const float4*)out_w,  (float4*)owr,  DD * DD / 4);

    // 1) QKV projection
    gemm_tf32_ldsm<<<dim3(N1 / 128, M1 / 128), 256, GEMM_SMEM>>>(tokr, wr, qkv_b, qkv_s, M1, N1, KD);
    // 2) RoPE + normalize (+SCALE*log2e on q) + bf16 q/k + V transpose
    rope_kernel<<<NBH * (SS / 64), 128>>>();
    // 3) flash attention (bf16 scores, tf32 PV)
    attn_bf16_ldsm<<<dim3(SS / 128, NBH), 256, ATTN_SMEM>>>(ao_s);
    // 4) output projection
    gemm_tf32_ldsm<<<dim3(DD / 128, M1 / 128), 256, GEMM_SMEM>>>(ao_s, owr, out_b, out, M1, DD, KD);
}

// round 8
// speedup vs baseline: 4.6820x; 1.1786x over previous
#include <cuda_runtime.h>
#include <cuda_fp16.h>
#include <math.h>

#define BB 2
#define SS 2048
#define DD 1024
#define HH 16
#define HD 64
#define M1 (BB*SS)      // 4096
#define N1 (3*DD)       // 3072
#define KD DD           // 1024
#define NBH (BB*HH)     // 32
#define SCALE 0.125f
#define LOG2E 1.44269504088896340736f

// ---------------- scratch (device globals; no allocations allowed) ----------
__device__ float g_qkv[(size_t)M1 * N1];
__device__ __half g_q[(size_t)NBH * SS * HD];   // [bh][s][d], fp16, pre-scaled SCALE*log2e
__device__ __half g_k[(size_t)NBH * SS * HD];   // [bh][s][d], fp16
__device__ __half g_v[(size_t)NBH * HD * SS];   // [bh][d][s], fp16 (transposed)
__device__ float g_ao[(size_t)BB * SS * DD];    // tf32
__device__ float g_tokr[(size_t)M1 * KD];
__device__ float g_wr[(size_t)N1 * KD];
__device__ float g_owr[(size_t)DD * DD];

// ---------------- helpers ----------------------------------------------------
__device__ __forceinline__ unsigned f2tf(float x) {
    unsigned u;
    asm("cvt.rna.tf32.f32 %0, %1;" : "=r"(u) : "f"(x));
    return u;
}
__device__ __forceinline__ float rtf(float x) { return __uint_as_float(f2tf(x)); }
__device__ __forceinline__ float ex2(float x) {
    float y;
    asm("ex2.approx.ftz.f32 %0, %1;" : "=f"(y) : "f"(x));
    return y;
}
__device__ __forceinline__ unsigned pack_h2(float lo, float hi) {
    __half2 h = __floats2half2_rn(lo, hi);
    return *(unsigned*)&h;
}
__device__ __forceinline__ void mma_tf32(float* c,
    unsigned a0, unsigned a1, unsigned a2, unsigned a3,
    unsigned b0, unsigned b1)
{
    asm volatile(
        "mma.sync.aligned.m16n8k8.row.col.f32.tf32.tf32.f32 "
        "{%0,%1,%2,%3},{%4,%5,%6,%7},{%8,%9},{%0,%1,%2,%3};"
        : "+f"(c[0]), "+f"(c[1]), "+f"(c[2]), "+f"(c[3])
        : "r"(a0), "r"(a1), "r"(a2), "r"(a3), "r"(b0), "r"(b1));
}
__device__ __forceinline__ void mma_f16(float* c,
    unsigned a0, unsigned a1, unsigned a2, unsigned a3,
    unsigned b0, unsigned b1)
{
    asm volatile(
        "mma.sync.aligned.m16n8k16.row.col.f32.f16.f16.f32 "
        "{%0,%1,%2,%3},{%4,%5,%6,%7},{%8,%9},{%0,%1,%2,%3};"
        : "+f"(c[0]), "+f"(c[1]), "+f"(c[2]), "+f"(c[3])
        : "r"(a0), "r"(a1), "r"(a2), "r"(a3), "r"(b0), "r"(b1));
}
__device__ __forceinline__ void cp16(unsigned s, const void* g) {
    asm volatile("cp.async.cg.shared.global [%0], [%1], 16;" :: "r"(s), "l"(g));
}
__device__ __forceinline__ void cp_commit() {
    asm volatile("cp.async.commit_group;");
}
template<int N> __device__ __forceinline__ void cp_wait() {
    asm volatile("cp.async.wait_group %0;" :: "n"(N));
}
#define LDSM4(r0, r1, r2, r3, addr) \
    asm volatile("ldmatrix.sync.aligned.m8n8.x4.shared.b16 {%0,%1,%2,%3}, [%4];" \
        : "=r"(r0), "=r"(r1), "=r"(r2), "=r"(r3) : "r"(addr))

// ---------------- tf32 rounding pass: 3 tensors in one launch ---------------
__global__ void round3_kernel(const float4* s0, float4* d0, int n0,
                              const float4* s1, float4* d1, int n1,
                              const float4* s2, float4* d2, int n2)
{
    const int total = n0 + n1 + n2;
    for (int i = blockIdx.x * blockDim.x + threadIdx.x; i < total;
         i += gridDim.x * blockDim.x) {
        const float4* s; float4* d; int j = i;
        if (j < n0) { s = s0; d = d0; }
        else if ((j -= n0) < n1) { s = s1; d = d1; }
        else { j -= n1; s = s2; d = d2; }
        float4 v = s[j];
        v.x = rtf(v.x); v.y = rtf(v.y); v.z = rtf(v.z); v.w = rtf(v.w);
        d[j] = v;
    }
}

// ---------------- tf32 GEMM: BK=32, 3-stage cp.async, ldmatrix --------------
#define GPW 36
#define GSTG (128 * GPW)
#define GEMM_SMEM (3 * 2 * GSTG * 4)      // 110592 bytes

__global__ __launch_bounds__(256, 2) void gemm_tf32_ldsm(
    const float* __restrict__ A, const float* __restrict__ W,
    const float* __restrict__ bias, float* __restrict__ C,
    int M, int N, int K)
{
    extern __shared__ __align__(16) unsigned gsm[];
    const unsigned sA_u = (unsigned)__cvta_generic_to_shared(gsm);
    const unsigned sB_u = sA_u + 3 * GSTG * 4;

    const int tid = threadIdx.x;
    const int bm = blockIdx.y << 7;
    const int bn = blockIdx.x << 7;
    const int w = tid >> 5;
    const int lane = tid & 31;
    const int wm = (w & 1) << 6;
    const int wn = (w >> 1) << 5;
    const int fr = lane >> 2;
    const int fc = lane & 3;

    const int lrow = tid >> 1;
    const int cb = (tid & 1) << 4;
    const float* Asrc = A + (size_t)(bm + lrow) * K + cb;
    const float* Wsrc = W + (size_t)(bn + lrow) * K + cb;
    const unsigned dA0 = sA_u + (lrow * GPW + cb) * 4;
    const unsigned dB0 = sB_u + (lrow * GPW + cb) * 4;

    const unsigned a_off = ((wm + (lane & 15)) * GPW + ((lane >> 4) << 2)) * 4;
    const unsigned b_off = ((wn + (lane & 7) + ((lane >> 4) << 3)) * GPW
                            + ((lane & 8) ? 4 : 0)) * 4;

    float acc[4][4][4];
#pragma unroll
    for (int mt = 0; mt < 4; mt++)
#pragma unroll
        for (int nt = 0; nt < 4; nt++)
#pragma unroll
            for (int i = 0; i < 4; i++) acc[mt][nt][i] = 0.f;

    const int nk = K >> 5;
    auto issue = [&](int kt) {
        const unsigned so = (kt % 3) * GSTG * 4;
        const float* a = Asrc + ((size_t)kt << 5);
        const float* b = Wsrc + ((size_t)kt << 5);
#pragma unroll
        for (int t = 0; t < 4; t++) {
            cp16(dA0 + so + t * 16, a + t * 4);
            cp16(dB0 + so + t * 16, b + t * 4);
        }
        cp_commit();
    };

    issue(0); issue(1);

    for (int kt = 0; kt < nk; kt++) {
        if (kt + 1 < nk) cp_wait<1>(); else cp_wait<0>();
        __syncthreads();
        if (kt + 2 < nk) issue(kt + 2);

        const unsigned sa = sA_u + (kt % 3) * GSTG * 4;
        const unsigned sb = sB_u + (kt % 3) * GSTG * 4;
#pragma unroll
        for (int ks = 0; ks < 4; ks++) {
            const unsigned kbb = ks * 32;
            unsigned af[4][4], bf[4][2];
#pragma unroll
            for (int mt = 0; mt < 4; mt++)
                LDSM4(af[mt][0], af[mt][1], af[mt][2], af[mt][3],
                      sa + a_off + mt * (16 * GPW * 4) + kbb);
#pragma unroll
            for (int p = 0; p < 2; p++)
                LDSM4(bf[2*p][0], bf[2*p][1], bf[2*p+1][0], bf[2*p+1][1],
                      sb + b_off + p * (16 * GPW * 4) + kbb);
#pragma unroll
            for (int mt = 0; mt < 4; mt++)
#pragma unroll
                for (int nt = 0; nt < 4; nt++)
                    mma_tf32(acc[mt][nt], af[mt][0], af[mt][1], af[mt][2], af[mt][3],
                             bf[nt][0], bf[nt][1]);
        }
    }

#pragma unroll
    for (int mt = 0; mt < 4; mt++) {
        const int row = bm + wm + (mt << 4) + fr;
#pragma unroll
        for (int nt = 0; nt < 4; nt++) {
            const int col = bn + wn + (nt << 3) + (fc << 1);
            *(float2*)(C + (size_t)row * N + col) =
                make_float2(acc[mt][nt][0] + bias[col], acc[mt][nt][1] + bias[col + 1]);
            *(float2*)(C + (size_t)(row + 8) * N + col) =
                make_float2(acc[mt][nt][2] + bias[col], acc[mt][nt][3] + bias[col + 1]);
        }
    }
}

// ---------------- RoPE + L2-norm + fp16 q/k + fp16 V transpose --------------
__global__ __launch_bounds__(128) void rope_kernel()
{
    __shared__ float sVt[64][65];
    const int tid = threadIdx.x;
    const int w = tid >> 5;
    const int f = tid & 31;
    const int blk = blockIdx.x;
    const int bh = blk >> 5;
    const int s0 = (blk & 31) << 6;
    const int b = bh >> 4, h = bh & 15;

    const double invd = exp(-(double)f * (9.210340371976184 / 32.0));

#pragma unroll 1
    for (int t = 0; t < 16; t++) {
        const int sl = (w << 4) + t;
        const int s = s0 + sl;
        float sn, cs;
        sincosf((float)((double)s * invd), &sn, &cs);

        const float* src = g_qkv + (size_t)(b * SS + s) * N1 + h * HD;
        float2 qv = *(const float2*)(src + 2 * f);
        float2 kv = *(const float2*)(src + DD + 2 * f);
        float2 vv = *(const float2*)(src + 2 * DD + 2 * f);

        const size_t dst = ((size_t)bh * SS + s) * HD + 2 * f;
        {
            float re = qv.x * cs - qv.y * sn;
            float ro = qv.x * sn + qv.y * cs;
            float sq = re * re + ro * ro;
#pragma unroll
            for (int msk = 16; msk > 0; msk >>= 1) sq += __shfl_xor_sync(0xffffffffu, sq, msk);
            float inv = (SCALE * LOG2E) / fmaxf(sqrtf(sq), 1e-12f);
            *(__half2*)(g_q + dst) = __floats2half2_rn(re * inv, ro * inv);
        }
        {
            float re = kv.x * cs - kv.y * sn;
            float ro = kv.x * sn + kv.y * cs;
            float sq = re * re + ro * ro;
#pragma unroll
            for (int msk = 16; msk > 0; msk >>= 1) sq += __shfl_xor_sync(0xffffffffu, sq, msk);
            float inv = 1.0f / fmaxf(sqrtf(sq), 1e-12f);
            *(__half2*)(g_k + dst) = __floats2half2_rn(re * inv, ro * inv);
        }
        sVt[sl][2 * f]     = vv.x;
        sVt[sl][2 * f + 1] = vv.y;
    }
    __syncthreads();

#pragma unroll 1
    for (int t = 0; t < 16; t++) {
        const int d = (w << 4) + t;
        __half* dst = g_v + ((size_t)bh * HD + d) * SS + s0;
        dst[f]      = __float2half_rn(sVt[f][d]);
        dst[f + 32] = __float2half_rn(sVt[f + 32][d]);
    }
}

// ---------------- flash attention: all-fp16 MMA, P in registers -------------
// sK: fp16 [kv][d] pitch 72h, 2 stages; sV: fp16 [d][kv] pitch 72h, 2 stages;
// sQ: fp16 [m][d] pitch 72h (staging only).
#define KP2 72
#define KSTG (64 * KP2 * 2)                  // 9216 B
#define QSTG (128 * KP2 * 2)                 // 18432 B
#define ATTN_SMEM (4 * KSTG + QSTG)          // 55296 B

__global__ __launch_bounds__(256, 2) void attn_f16(float* __restrict__ Oo)
{
    extern __shared__ __align__(16) unsigned smem_[];
    const unsigned sK_u = (unsigned)__cvta_generic_to_shared(smem_);
    const unsigned sV_u = sK_u + 2 * KSTG;
    const unsigned sQ_u = sK_u + 4 * KSTG;

    const int tid = threadIdx.x;
    const int w = tid >> 5;
    const int lane = tid & 31;
    const int fr = lane >> 2;
    const int fc = lane & 3;
    const int bh = blockIdx.y;
    const int b = bh >> 4, h = bh & 15;
    const int q0 = blockIdx.x << 7;

    const __half* Qp = g_q + (size_t)bh * SS * HD;
    const __half* Kp = g_k + (size_t)bh * SS * HD;
    const __half* Vp = g_v + (size_t)bh * HD * SS;

    // cp.async coords: K/V 64 rows x 128B, Q 128 rows x 128B
    const int krow = tid >> 2;               // 0..63
    const int kc = tid & 3;
    const int qrow = tid >> 1;               // 0..127
    const int qc = tid & 1;

    auto issueKV = [&](int jt) {
        const unsigned soK = sK_u + (jt & 1) * KSTG;
        const unsigned soV = sV_u + (jt & 1) * KSTG;
        const __half* gK = Kp + (size_t)(jt * 64 + krow) * HD;
        const __half* gV = Vp + (size_t)krow * SS + jt * 64;
#pragma unroll
        for (int t = 0; t < 2; t++) {
            const int c = (kc + (t << 2)) << 3;   // half-col 0..56
            cp16(soK + (krow * KP2 + c) * 2, gK + c);
            cp16(soV + (krow * KP2 + c) * 2, gV + c);
        }
        cp_commit();
    };

    // stage Q
    {
        const __half* gQ = Qp + (size_t)(q0 + qrow) * HD;
#pragma unroll
        for (int t = 0; t < 4; t++) {
            const int c = ((qc << 2) + t) << 3;
            cp16(sQ_u + (qrow * KP2 + c) * 2, gQ + c);
        }
        cp_commit();
    }
    issueKV(0);

    cp_wait<1>();      // Q resident
    __syncthreads();

    // Q fragments (f16 A-frags m16n8k16), held in registers
    const unsigned a_q_off = (((w << 4) + (lane & 15)) * KP2 + ((lane >> 4) << 3)) * 2;
    unsigned qf[4][4];
#pragma unroll
    for (int ks = 0; ks < 4; ks++)
        LDSM4(qf[ks][0], qf[ks][1], qf[ks][2], qf[ks][3], sQ_u + a_q_off + ks * 32);

    // B-frag lane offset: rows (lane&7)+((lane>>4)<<3), col half-offset 8*((lane>>3)&1)
    const unsigned b_off = (((lane & 7) + ((lane >> 4) << 3)) * KP2
                            + (((lane >> 3) & 1) << 3)) * 2;

    float o[8][4];
#pragma unroll
    for (int nt = 0; nt < 8; nt++)
#pragma unroll
        for (int i = 0; i < 4; i++) o[nt][i] = 0.f;
    float mA = -1e30f, mB = -1e30f, lA = 0.f, lB = 0.f;

    const int NT = SS / 64;   // 32
    for (int jt = 0; jt < NT; jt++) {
        cp_wait<0>();
        __syncthreads();
        if (jt + 1 < NT) issueKV(jt + 1);

        const unsigned Ktu = sK_u + (jt & 1) * KSTG;
        const unsigned Vtu = sV_u + (jt & 1) * KSTG;

        // S = Q K^T (f16, 4 k16 steps)
        float s[8][4];
#pragma unroll
        for (int nt = 0; nt < 8; nt++)
#pragma unroll
            for (int i = 0; i < 4; i++) s[nt][i] = 0.f;
#pragma unroll
        for (int ks = 0; ks < 4; ks++) {
            unsigned bf[8][2];
#pragma unroll
            for (int ng = 0; ng < 4; ng++)
                LDSM4(bf[2*ng][0], bf[2*ng][1], bf[2*ng+1][0], bf[2*ng+1][1],
                      Ktu + b_off + ng * (16 * KP2 * 2) + ks * 32);
#pragma unroll
            for (int nt = 0; nt < 8; nt++)
                mma_f16(s[nt], qf[ks][0], qf[ks][1], qf[ks][2], qf[ks][3],
                        bf[nt][0], bf[nt][1]);
        }

        // online softmax (exp2 domain; q carries SCALE*log2e)
        float mxA = -1e30f, mxB = -1e30f;
#pragma unroll
        for (int nt = 0; nt < 8; nt++) {
            mxA = fmaxf(mxA, fmaxf(s[nt][0], s[nt][1]));
            mxB = fmaxf(mxB, fmaxf(s[nt][2], s[nt][3]));
        }
        mxA = fmaxf(mxA, __shfl_xor_sync(0xffffffffu, mxA, 1));
        mxA = fmaxf(mxA, __shfl_xor_sync(0xffffffffu, mxA, 2));
        mxB = fmaxf(mxB, __shfl_xor_sync(0xffffffffu, mxB, 1));
        mxB = fmaxf(mxB, __shfl_xor_sync(0xffffffffu, mxB, 2));
        const float nmA = fmaxf(mA, mxA);
        const float nmB = fmaxf(mB, mxB);
        const float sclA = ex2(mA - nmA);
        const float sclB = ex2(mB - nmB);
        float sumA = 0.f, sumB = 0.f;
#pragma unroll
        for (int nt = 0; nt < 8; nt++) {
            s[nt][0] = ex2(s[nt][0] - nmA);
            s[nt][1] = ex2(s[nt][1] - nmA);
            s[nt][2] = ex2(s[nt][2] - nmB);
            s[nt][3] = ex2(s[nt][3] - nmB);
            sumA += s[nt][0] + s[nt][1];
            sumB += s[nt][2] + s[nt][3];
        }
        sumA += __shfl_xor_sync(0xffffffffu, sumA, 1);
        sumA += __shfl_xor_sync(0xffffffffu, sumA, 2);
        sumB += __shfl_xor_sync(0xffffffffu, sumB, 1);
        sumB += __shfl_xor_sync(0xffffffffu, sumB, 2);
        lA = lA * sclA + sumA;  mA = nmA;
        lB = lB * sclB + sumB;  mB = nmB;
#pragma unroll
        for (int nt = 0; nt < 8; nt++) {
            o[nt][0] *= sclA; o[nt][1] *= sclA;
            o[nt][2] *= sclB; o[nt][3] *= sclB;
        }

        // O += P @ V : P stays in registers (C-frag == A-frag for f16 k16)
#pragma unroll
        for (int ks = 0; ks < 4; ks++) {
            const unsigned a0 = pack_h2(s[2*ks][0],   s[2*ks][1]);
            const unsigned a1 = pack_h2(s[2*ks][2],   s[2*ks][3]);
            const unsigned a2 = pack_h2(s[2*ks+1][0], s[2*ks+1][1]);
            const unsigned a3 = pack_h2(s[2*ks+1][2], s[2*ks+1][3]);
            unsigned vf[8][2];
#pragma unroll
            for (int p = 0; p < 4; p++)
                LDSM4(vf[2*p][0], vf[2*p][1], vf[2*p+1][0], vf[2*p+1][1],
                      Vtu + b_off + p * (16 * KP2 * 2) + ks * 32);
#pragma unroll
            for (int nt = 0; nt < 8; nt++)
                mma_f16(o[nt], a0, a1, a2, a3, vf[nt][0], vf[nt][1]);
        }
    }

    // epilogue: normalize + tf32 round (feeds out-proj)
    const float invA = 1.0f / lA;
    const float invB = 1.0f / lB;
    float* Op = Oo + (size_t)b * SS * DD + h * HD;
    const int ra = q0 + (w << 4) + fr;
#pragma unroll
    for (int nt = 0; nt < 8; nt++) {
        const int col = (nt << 3) + (fc << 1);
        *(float2*)(Op + (size_t)ra * DD + col) =
            make_float2(rtf(o[nt][0] * invA), rtf(o[nt][1] * invA));
        *(float2*)(Op + (size_t)(ra + 8) * DD + col) =
            make_float2(rtf(o[nt][2] * invB), rtf(o[nt][3] * invB));
    }
}

// ---------------- launch ----------------------------------------------------
extern "C" void kernel_launch(void* const* d_in, const int* in_sizes, int n_in,
                              void* d_out, int out_size)
{
    (void)in_sizes; (void)n_in; (void)out_size;
    const float* tokens = (const float*)d_in[0];
    const float* qkv_w  = (const float*)d_in[1];
    const float* qkv_b  = (const float*)d_in[2];
    const float* out_w  = (const float*)d_in[3];
    const float* out_b  = (const float*)d_in[4];
    float* out = (float*)d_out;

    float *qkv_s, *ao_s, *tokr, *wr, *owr;
    cudaGetSymbolAddress((void**)&qkv_s, g_qkv);
    cudaGetSymbolAddress((void**)&ao_s, g_ao);
    cudaGetSymbolAddress((void**)&tokr, g_tokr);
    cudaGetSymbolAddress((void**)&wr, g_wr);
    cudaGetSymbolAddress((void**)&owr, g_owr);

    static int smem_set = 0;
    if (!smem_set) {
        cudaFuncSetAttribute(gemm_tf32_ldsm, cudaFuncAttributeMaxDynamicSharedMemorySize, GEMM_SMEM);
        cudaFuncSetAttribute(attn_f16, cudaFuncAttributeMaxDynamicSharedMemorySize, ATTN_SMEM);
        smem_set = 1;
    }

    // 0) pre-round GEMM operands to tf32 (rna)
    round3_kernel<<<2048, 256>>>(
        (const float4*)tokens, (float4*)tokr, M1 * KD / 4,
        (const float4*)qkv_w,  (float4*)wr,   N1 * KD / 4,
        (const float4*)out_w,  (float4*)owr,  DD * DD / 4);

    // 1) QKV projection
    gemm_tf32_ldsm<<<dim3(N1 / 128, M1 / 128), 256, GEMM_SMEM>>>(tokr, wr, qkv_b, qkv_s, M1, N1, KD);
    // 2) RoPE + normalize (+SCALE*log2e on q) + fp16 q/k/v + V transpose
    rope_kernel<<<NBH * (SS / 64), 128>>>();
    // 3) flash attention (fp16 MMAs, P in registers)
    attn_f16<<<dim3(SS / 128, NBH), 256, ATTN_SMEM>>>(ao_s);
    // 4) output projection
    gemm_tf32_ldsm<<<dim3(DD / 128, M1 / 128), 256, GEMM_SMEM>>>(ao_s, owr, out_b, out, M1, DD, KD);
}

// round 9
// speedup vs baseline: 6.8483x; 1.4627x over previous
#include <cuda_runtime.h>
#include <cuda_fp16.h>
#include <math.h>

#define BB 2
#define SS 2048
#define DD 1024
#define HH 16
#define HD 64
#define M1 (BB*SS)      // 4096
#define N1 (3*DD)       // 3072
#define KD DD           // 1024
#define NBH (BB*HH)     // 32
#define SCALE 0.125f
#define LOG2E 1.44269504088896340736f

// ---------------- scratch (device globals; no allocations allowed) ----------
__device__ __half g_qkv[(size_t)M1 * N1];       // [4096,3072] fp16
__device__ __half g_q[(size_t)NBH * SS * HD];   // [bh][s][d] fp16, pre-scaled SCALE*log2e
__device__ __half g_k[(size_t)NBH * SS * HD];   // [bh][s][d] fp16
__device__ __half g_v[(size_t)NBH * HD * SS];   // [bh][d][s] fp16 (transposed)
__device__ __half g_ao[(size_t)BB * SS * DD];   // [B,S,D] fp16 (attention out)
__device__ __half g_tokh[(size_t)M1 * KD];      // fp16 tokens
__device__ __half g_wh[(size_t)N1 * KD];        // fp16 qkv_w
__device__ __half g_owh[(size_t)DD * DD];       // fp16 out_w

// ---------------- helpers ----------------------------------------------------
__device__ __forceinline__ float ex2(float x) {
    float y;
    asm("ex2.approx.ftz.f32 %0, %1;" : "=f"(y) : "f"(x));
    return y;
}
__device__ __forceinline__ unsigned pack_h2(float lo, float hi) {
    __half2 h = __floats2half2_rn(lo, hi);
    return *(unsigned*)&h;
}
__device__ __forceinline__ void mma_f16(float* c,
    unsigned a0, unsigned a1, unsigned a2, unsigned a3,
    unsigned b0, unsigned b1)
{
    asm volatile(
        "mma.sync.aligned.m16n8k16.row.col.f32.f16.f16.f32 "
        "{%0,%1,%2,%3},{%4,%5,%6,%7},{%8,%9},{%0,%1,%2,%3};"
        : "+f"(c[0]), "+f"(c[1]), "+f"(c[2]), "+f"(c[3])
        : "r"(a0), "r"(a1), "r"(a2), "r"(a3), "r"(b0), "r"(b1));
}
__device__ __forceinline__ void cp16(unsigned s, const void* g) {
    asm volatile("cp.async.cg.shared.global [%0], [%1], 16;" :: "r"(s), "l"(g));
}
__device__ __forceinline__ void cp_commit() {
    asm volatile("cp.async.commit_group;");
}
template<int N> __device__ __forceinline__ void cp_wait() {
    asm volatile("cp.async.wait_group %0;" :: "n"(N));
}
#define LDSM4(r0, r1, r2, r3, addr) \
    asm volatile("ldmatrix.sync.aligned.m8n8.x4.shared.b16 {%0,%1,%2,%3}, [%4];" \
        : "=r"(r0), "=r"(r1), "=r"(r2), "=r"(r3) : "r"(addr))

// ---------------- fp16 conversion pass: 3 tensors in one launch -------------
__global__ void tohalf3_kernel(const float4* s0, __half2* d0, int n0,
                               const float4* s1, __half2* d1, int n1,
                               const float4* s2, __half2* d2, int n2)
{
    const int total = n0 + n1 + n2;
    for (int i = blockIdx.x * blockDim.x + threadIdx.x; i < total;
         i += gridDim.x * blockDim.x) {
        const float4* s; __half2* d; int j = i;
        if (j < n0) { s = s0; d = d0; }
        else if ((j -= n0) < n1) { s = s1; d = d1; }
        else { j -= n1; s = s2; d = d2; }
        float4 v = s[j];
        d[2 * j]     = __floats2half2_rn(v.x, v.y);
        d[2 * j + 1] = __floats2half2_rn(v.z, v.w);
    }
}

// ---------------- fp16 GEMM: BK=64, 3-stage cp.async, ldmatrix --------------
// C[M,N] = A[M,K] @ W[N,K]^T + bias (fp32 bias/accum).
// smem stage: [128 rows][64 k + 8 pad] halves (pitch 72 -> conflict-free).
#define GKP 72
#define GSTG (128 * GKP * 2)                  // 18432 B / tensor / stage
#define GEMM_SMEM (3 * 2 * GSTG)              // 110592 B

template<bool HALF_OUT>
__global__ __launch_bounds__(256, 2) void gemm_f16_ldsm(
    const __half* __restrict__ A, const __half* __restrict__ W,
    const float* __restrict__ bias, void* __restrict__ Cv,
    int M, int N, int K)
{
    extern __shared__ __align__(16) unsigned gsm[];
    const unsigned sA_u = (unsigned)__cvta_generic_to_shared(gsm);
    const unsigned sB_u = sA_u + 3 * GSTG;

    const int tid = threadIdx.x;
    const int bm = blockIdx.y << 7;
    const int bn = blockIdx.x << 7;
    const int w = tid >> 5;
    const int lane = tid & 31;
    const int wm = (w & 1) << 6;
    const int wn = (w >> 1) << 5;
    const int fr = lane >> 2;
    const int fc = lane & 3;

    // loader: 128 rows x 128B per tensor; 2 threads/row, 4 chunks each
    const int lrow = tid >> 1;
    const int lc4 = (tid & 1) << 2;        // chunk base 0 or 4
    const __half* Asrc = A + (size_t)(bm + lrow) * K;
    const __half* Wsrc = W + (size_t)(bn + lrow) * K;
    const unsigned dA0 = sA_u + lrow * GKP * 2;
    const unsigned dB0 = sB_u + lrow * GKP * 2;

    // ldmatrix lane offsets
    const unsigned a_off = ((wm + (lane & 15)) * GKP + ((lane >> 4) << 3)) * 2;
    const unsigned b_off = (((wn >> 5) * 0 + (lane & 7) + ((lane >> 4) << 3) + wn) * GKP
                            + (((lane >> 3) & 1) << 3)) * 2;

    float acc[4][4][4];
#pragma unroll
    for (int mt = 0; mt < 4; mt++)
#pragma unroll
        for (int nt = 0; nt < 4; nt++)
#pragma unroll
            for (int i = 0; i < 4; i++) acc[mt][nt][i] = 0.f;

    const int nk = K >> 6;   // BK=64
    auto issue = [&](int kt) {
        const unsigned so = (kt % 3) * GSTG;
        const __half* a = Asrc + ((size_t)kt << 6);
        const __half* b = Wsrc + ((size_t)kt << 6);
#pragma unroll
        for (int t = 0; t < 4; t++) {
            const int c = (lc4 + t) << 3;       // half offset 0..56
            cp16(dA0 + so + c * 2, a + c);
            cp16(dB0 + so + c * 2, b + c);
        }
        cp_commit();
    };

    issue(0); issue(1);

    for (int kt = 0; kt < nk; kt++) {
        if (kt + 1 < nk) cp_wait<1>(); else cp_wait<0>();
        __syncthreads();
        if (kt + 2 < nk) issue(kt + 2);

        const unsigned sa = sA_u + (kt % 3) * GSTG;
        const unsigned sb = sB_u + (kt % 3) * GSTG;
#pragma unroll
        for (int ks = 0; ks < 4; ks++) {
            const unsigned kbb = ks * 32;       // 16 halves
            unsigned af[4][4], bf[4][2];
#pragma unroll
            for (int mt = 0; mt < 4; mt++)
                LDSM4(af[mt][0], af[mt][1], af[mt][2], af[mt][3],
                      sa + a_off + mt * (16 * GKP * 2) + kbb);
#pragma unroll
            for (int p = 0; p < 2; p++)
                LDSM4(bf[2*p][0], bf[2*p][1], bf[2*p+1][0], bf[2*p+1][1],
                      sb + b_off + p * (16 * GKP * 2) + kbb);
#pragma unroll
            for (int mt = 0; mt < 4; mt++)
#pragma unroll
                for (int nt = 0; nt < 4; nt++)
                    mma_f16(acc[mt][nt], af[mt][0], af[mt][1], af[mt][2], af[mt][3],
                            bf[nt][0], bf[nt][1]);
        }
    }

#pragma unroll
    for (int mt = 0; mt < 4; mt++) {
        const int row = bm + wm + (mt << 4) + fr;
#pragma unroll
        for (int nt = 0; nt < 4; nt++) {
            const int col = bn + wn + (nt << 3) + (fc << 1);
            const float b0 = bias[col], b1 = bias[col + 1];
            if (HALF_OUT) {
                __half* C = (__half*)Cv;
                *(__half2*)(C + (size_t)row * N + col) =
                    __floats2half2_rn(acc[mt][nt][0] + b0, acc[mt][nt][1] + b1);
                *(__half2*)(C + (size_t)(row + 8) * N + col) =
                    __floats2half2_rn(acc[mt][nt][2] + b0, acc[mt][nt][3] + b1);
            } else {
                float* C = (float*)Cv;
                *(float2*)(C + (size_t)row * N + col) =
                    make_float2(acc[mt][nt][0] + b0, acc[mt][nt][1] + b1);
                *(float2*)(C + (size_t)(row + 8) * N + col) =
                    make_float2(acc[mt][nt][2] + b0, acc[mt][nt][3] + b1);
            }
        }
    }
}

// ---------------- RoPE + L2-norm + fp16 q/k + fp16 V transpose --------------
__global__ __launch_bounds__(128) void rope_kernel()
{
    __shared__ float sVt[64][65];
    const int tid = threadIdx.x;
    const int w = tid >> 5;
    const int f = tid & 31;
    const int blk = blockIdx.x;
    const int bh = blk >> 5;
    const int s0 = (blk & 31) << 6;
    const int b = bh >> 4, h = bh & 15;

    const double invd = exp(-(double)f * (9.210340371976184 / 32.0));

#pragma unroll 1
    for (int t = 0; t < 16; t++) {
        const int sl = (w << 4) + t;
        const int s = s0 + sl;
        float sn, cs;
        sincosf((float)((double)s * invd), &sn, &cs);

        const __half* src = g_qkv + (size_t)(b * SS + s) * N1 + h * HD;
        float2 qv = __half22float2(*(const __half2*)(src + 2 * f));
        float2 kv = __half22float2(*(const __half2*)(src + DD + 2 * f));
        float2 vv = __half22float2(*(const __half2*)(src + 2 * DD + 2 * f));

        const size_t dst = ((size_t)bh * SS + s) * HD + 2 * f;
        {
            float re = qv.x * cs - qv.y * sn;
            float ro = qv.x * sn + qv.y * cs;
            float sq = re * re + ro * ro;
#pragma unroll
            for (int msk = 16; msk > 0; msk >>= 1) sq += __shfl_xor_sync(0xffffffffu, sq, msk);
            float inv = (SCALE * LOG2E) / fmaxf(sqrtf(sq), 1e-12f);
            *(__half2*)(g_q + dst) = __floats2half2_rn(re * inv, ro * inv);
        }
        {
            float re = kv.x * cs - kv.y * sn;
            float ro = kv.x * sn + kv.y * cs;
            float sq = re * re + ro * ro;
#pragma unroll
            for (int msk = 16; msk > 0; msk >>= 1) sq += __shfl_xor_sync(0xffffffffu, sq, msk);
            float inv = 1.0f / fmaxf(sqrtf(sq), 1e-12f);
            *(__half2*)(g_k + dst) = __floats2half2_rn(re * inv, ro * inv);
        }
        sVt[sl][2 * f]     = vv.x;
        sVt[sl][2 * f + 1] = vv.y;
    }
    __syncthreads();

#pragma unroll 1
    for (int t = 0; t < 16; t++) {
        const int d = (w << 4) + t;
        __half* dst = g_v + ((size_t)bh * HD + d) * SS + s0;
        dst[f]      = __float2half_rn(sVt[f][d]);
        dst[f + 32] = __float2half_rn(sVt[f + 32][d]);
    }
}

// ---------------- flash attention: all-fp16 MMA, P in registers -------------
#define KP2 72
#define KSTG (64 * KP2 * 2)                  // 9216 B
#define QSTG (128 * KP2 * 2)                 // 18432 B
#define ATTN_SMEM (4 * KSTG + QSTG)          // 55296 B

__global__ __launch_bounds__(256, 2) void attn_f16(__half* __restrict__ Oo)
{
    extern __shared__ __align__(16) unsigned smem_[];
    const unsigned sK_u = (unsigned)__cvta_generic_to_shared(smem_);
    const unsigned sV_u = sK_u + 2 * KSTG;
    const unsigned sQ_u = sK_u + 4 * KSTG;

    const int tid = threadIdx.x;
    const int w = tid >> 5;
    const int lane = tid & 31;
    const int fr = lane >> 2;
    const int fc = lane & 3;
    const int bh = blockIdx.y;
    const int b = bh >> 4, h = bh & 15;
    const int q0 = blockIdx.x << 7;

    const __half* Qp = g_q + (size_t)bh * SS * HD;
    const __half* Kp = g_k + (size_t)bh * SS * HD;
    const __half* Vp = g_v + (size_t)bh * HD * SS;

    const int krow = tid >> 2;               // 0..63
    const int kc = tid & 3;
    const int qrow = tid >> 1;               // 0..127
    const int qc = tid & 1;

    auto issueKV = [&](int jt) {
        const unsigned soK = sK_u + (jt & 1) * KSTG;
        const unsigned soV = sV_u + (jt & 1) * KSTG;
        const __half* gK = Kp + (size_t)(jt * 64 + krow) * HD;
        const __half* gV = Vp + (size_t)krow * SS + jt * 64;
#pragma unroll
        for (int t = 0; t < 2; t++) {
            const int c = (kc + (t << 2)) << 3;
            cp16(soK + (krow * KP2 + c) * 2, gK + c);
            cp16(soV + (krow * KP2 + c) * 2, gV + c);
        }
        cp_commit();
    };

    {
        const __half* gQ = Qp + (size_t)(q0 + qrow) * HD;
#pragma unroll
        for (int t = 0; t < 4; t++) {
            const int c = ((qc << 2) + t) << 3;
            cp16(sQ_u + (qrow * KP2 + c) * 2, gQ + c);
        }
        cp_commit();
    }
    issueKV(0);

    cp_wait<1>();
    __syncthreads();

    const unsigned a_q_off = (((w << 4) + (lane & 15)) * KP2 + ((lane >> 4) << 3)) * 2;
    unsigned qf[4][4];
#pragma unroll
    for (int ks = 0; ks < 4; ks++)
        LDSM4(qf[ks][0], qf[ks][1], qf[ks][2], qf[ks][3], sQ_u + a_q_off + ks * 32);

    const unsigned b_off = (((lane & 7) + ((lane >> 4) << 3)) * KP2
                            + (((lane >> 3) & 1) << 3)) * 2;

    float o[8][4];
#pragma unroll
    for (int nt = 0; nt < 8; nt++)
#pragma unroll
        for (int i = 0; i < 4; i++) o[nt][i] = 0.f;
    float mA = -1e30f, mB = -1e30f, lA = 0.f, lB = 0.f;

    const int NT = SS / 64;
    for (int jt = 0; jt < NT; jt++) {
        cp_wait<0>();
        __syncthreads();
        if (jt + 1 < NT) issueKV(jt + 1);

        const unsigned Ktu = sK_u + (jt & 1) * KSTG;
        const unsigned Vtu = sV_u + (jt & 1) * KSTG;

        float s[8][4];
#pragma unroll
        for (int nt = 0; nt < 8; nt++)
#pragma unroll
            for (int i = 0; i < 4; i++) s[nt][i] = 0.f;
#pragma unroll
        for (int ks = 0; ks < 4; ks++) {
            unsigned bf[8][2];
#pragma unroll
            for (int ng = 0; ng < 4; ng++)
                LDSM4(bf[2*ng][0], bf[2*ng][1], bf[2*ng+1][0], bf[2*ng+1][1],
                      Ktu + b_off + ng * (16 * KP2 * 2) + ks * 32);
#pragma unroll
            for (int nt = 0; nt < 8; nt++)
                mma_f16(s[nt], qf[ks][0], qf[ks][1], qf[ks][2], qf[ks][3],
                        bf[nt][0], bf[nt][1]);
        }

        float mxA = -1e30f, mxB = -1e30f;
#pragma unroll
        for (int nt = 0; nt < 8; nt++) {
            mxA = fmaxf(mxA, fmaxf(s[nt][0], s[nt][1]));
            mxB = fmaxf(mxB, fmaxf(s[nt][2], s[nt][3]));
        }
        mxA = fmaxf(mxA, __shfl_xor_sync(0xffffffffu, mxA, 1));
        mxA = fmaxf(mxA, __shfl_xor_sync(0xffffffffu, mxA, 2));
        mxB = fmaxf(mxB, __shfl_xor_sync(0xffffffffu, mxB, 1));
        mxB = fmaxf(mxB, __shfl_xor_sync(0xffffffffu, mxB, 2));
        const float nmA = fmaxf(mA, mxA);
        const float nmB = fmaxf(mB, mxB);
        const float sclA = ex2(mA - nmA);
        const float sclB = ex2(mB - nmB);
        float sumA = 0.f, sumB = 0.f;
#pragma unroll
        for (int nt = 0; nt < 8; nt++) {
            s[nt][0] = ex2(s[nt][0] - nmA);
            s[nt][1] = ex2(s[nt][1] - nmA);
            s[nt][2] = ex2(s[nt][2] - nmB);
            s[nt][3] = ex2(s[nt][3] - nmB);
            sumA += s[nt][0] + s[nt][1];
            sumB += s[nt][2] + s[nt][3];
        }
        sumA += __shfl_xor_sync(0xffffffffu, sumA, 1);
        sumA += __shfl_xor_sync(0xffffffffu, sumA, 2);
        sumB += __shfl_xor_sync(0xffffffffu, sumB, 1);
        sumB += __shfl_xor_sync(0xffffffffu, sumB, 2);
        lA = lA * sclA + sumA;  mA = nmA;
        lB = lB * sclB + sumB;  mB = nmB;
#pragma unroll
        for (int nt = 0; nt < 8; nt++) {
            o[nt][0] *= sclA; o[nt][1] *= sclA;
            o[nt][2] *= sclB; o[nt][3] *= sclB;
        }

        // O += P @ V : P stays in registers
#pragma unroll
        for (int ks = 0; ks < 4; ks++) {
            const unsigned a0 = pack_h2(s[2*ks][0],   s[2*ks][1]);
            const unsigned a1 = pack_h2(s[2*ks][2],   s[2*ks][3]);
            const unsigned a2 = pack_h2(s[2*ks+1][0], s[2*ks+1][1]);
            const unsigned a3 = pack_h2(s[2*ks+1][2], s[2*ks+1][3]);
            unsigned vf[8][2];
#pragma unroll
            for (int p = 0; p < 4; p++)
                LDSM4(vf[2*p][0], vf[2*p][1], vf[2*p+1][0], vf[2*p+1][1],
                      Vtu + b_off + p * (16 * KP2 * 2) + ks * 32);
#pragma unroll
            for (int nt = 0; nt < 8; nt++)
                mma_f16(o[nt], a0, a1, a2, a3, vf[nt][0], vf[nt][1]);
        }
    }

    // epilogue: normalize, write fp16 (feeds out-proj)
    const float invA = 1.0f / lA;
    const float invB = 1.0f / lB;
    __half* Op = Oo + (size_t)b * SS * DD + h * HD;
    const int ra = q0 + (w << 4) + fr;
#pragma unroll
    for (int nt = 0; nt < 8; nt++) {
        const int col = (nt << 3) + (fc << 1);
        *(__half2*)(Op + (size_t)ra * DD + col) =
            __floats2half2_rn(o[nt][0] * invA, o[nt][1] * invA);
        *(__half2*)(Op + (size_t)(ra + 8) * DD + col) =
            __floats2half2_rn(o[nt][2] * invB, o[nt][3] * invB);
    }
}

// ---------------- launch ----------------------------------------------------
extern "C" void kernel_launch(void* const* d_in, const int* in_sizes, int n_in,
                              void* d_out, int out_size)
{
    (void)in_sizes; (void)n_in; (void)out_size;
    const float* tokens = (const float*)d_in[0];
    const float* qkv_w  = (const float*)d_in[1];
    const float* qkv_b  = (const float*)d_in[2];
    const float* out_w  = (const float*)d_in[3];
    const float* out_b  = (const float*)d_in[4];
    float* out = (float*)d_out;

    __half *qkv_s, *ao_s, *tokh, *wh, *owh;
    cudaGetSymbolAddress((void**)&qkv_s, g_qkv);
    cudaGetSymbolAddress((void**)&ao_s, g_ao);
    cudaGetSymbolAddress((void**)&tokh, g_tokh);
    cudaGetSymbolAddress((void**)&wh, g_wh);
    cudaGetSymbolAddress((void**)&owh, g_owh);

    static int smem_set = 0;
    if (!smem_set) {
        cudaFuncSetAttribute(gemm_f16_ldsm<true>, cudaFuncAttributeMaxDynamicSharedMemorySize, GEMM_SMEM);
        cudaFuncSetAttribute(gemm_f16_ldsm<false>, cudaFuncAttributeMaxDynamicSharedMemorySize, GEMM_SMEM);
        cudaFuncSetAttribute(attn_f16, cudaFuncAttributeMaxDynamicSharedMemorySize, ATTN_SMEM);
        smem_set = 1;
    }

    // 0) convert GEMM operands to fp16 (rn; same 10-bit mantissa as tf32)
    tohalf3_kernel<<<2048, 256>>>(
        (const float4*)tokens, (__half2*)tokh, M1 * KD / 4,
        (const float4*)qkv_w,  (__half2*)wh,   N1 * KD / 4,
        (const float4*)out_w,  (__half2*)owh,  DD * DD / 4);

    // 1) QKV projection (fp16 MMA, fp32 accum, fp16 out)
    gemm_f16_ldsm<true><<<dim3(N1 / 128, M1 / 128), 256, GEMM_SMEM>>>(
        tokh, wh, qkv_b, qkv_s, M1, N1, KD);
    // 2) RoPE + normalize (+SCALE*log2e on q) + fp16 q/k/v + V transpose
    rope_kernel<<<NBH * (SS / 64), 128>>>();
    // 3) flash attention (fp16 MMAs, P in registers, fp16 out)
    attn_f16<<<dim3(SS / 128, NBH), 256, ATTN_SMEM>>>(ao_s);
    // 4) output projection (fp16 MMA, fp32 accum + bias, fp32 out)
    gemm_f16_ldsm<false><<<dim3(DD / 128, M1 / 128), 256, GEMM_SMEM>>>(
        ao_s, owh, out_b, out, M1, DD, KD);
}